// round 1
// baseline (speedup 1.0000x reference)
#include <cuda_runtime.h>

// Problem constants
#define B_  2
#define T_  2048
#define C_  1024
#define H_  16
#define HD_ 64
#define NR  (B_*T_)          // 4096 rows
#define FF  (4*C_)           // 4096

// ---------------- scratch (no allocations allowed) ----------------
__device__ float g_h  [NR*C_];   // ln1 out
__device__ float g_q  [NR*C_];
__device__ float g_k  [NR*C_];
__device__ float g_v  [NR*C_];
__device__ float g_att[NR*C_];
__device__ float g_x2 [NR*C_];   // post-attention residual
__device__ float g_h2 [NR*C_];   // ln2 out
__device__ float g_ff1[NR*FF];   // relu(h2@W1+b1)

// ---------------- block reduction (256 threads) ----------------
__device__ __forceinline__ float block_sum256(float v) {
    __shared__ float red[8];
    #pragma unroll
    for (int o = 16; o; o >>= 1) v += __shfl_xor_sync(0xffffffffu, v, o);
    __syncthreads();                      // protect red from previous use
    if ((threadIdx.x & 31) == 0) red[threadIdx.x >> 5] = v;
    __syncthreads();
    float s = 0.f;
    #pragma unroll
    for (int i = 0; i < 8; i++) s += red[i];
    return s;
}

// ---------------- LayerNorm: one block per row ----------------
__global__ void ln_kernel(const float* __restrict__ x,
                          const float* __restrict__ g,
                          const float* __restrict__ b,
                          float* __restrict__ out) {
    int row = blockIdx.x;
    const float4* xr = (const float4*)(x + (size_t)row * C_);
    float4 xa = xr[threadIdx.x];

    float s = xa.x + xa.y + xa.z + xa.w;
    float mu = block_sum256(s) * (1.0f / C_);

    float dx = xa.x - mu, dy = xa.y - mu, dz = xa.z - mu, dw = xa.w - mu;
    float sq = dx*dx + dy*dy + dz*dz + dw*dw;
    float var = block_sum256(sq) * (1.0f / C_);
    float rstd = rsqrtf(var + 1e-5f);

    float4 gg = ((const float4*)g)[threadIdx.x];
    float4 bb = ((const float4*)b)[threadIdx.x];
    float4 o;
    o.x = dx * rstd * gg.x + bb.x;
    o.y = dy * rstd * gg.y + bb.y;
    o.z = dz * rstd * gg.z + bb.z;
    o.w = dw * rstd * gg.w + bb.w;
    ((float4*)(out + (size_t)row * C_))[threadIdx.x] = o;
}

// ---------------- GEMM: C = A[MxK] @ B[KxN] (+bias)(+relu)(+residual) ------
// BM=128, BN=64, BK=16, 256 threads, 8x4 micro-tile per thread.
// EPI: 0 = none, 1 = bias + relu, 2 = bias + residual
template <int EPI>
__global__ void gemm_kernel(const float* __restrict__ A,
                            const float* __restrict__ Bm,
                            const float* __restrict__ bias,
                            const float* __restrict__ res,
                            float* __restrict__ Cm,
                            int M, int N, int K) {
    __shared__ float As[16][128];   // [k][m]
    __shared__ float Bs[16][64];    // [k][n]

    const int tx   = threadIdx.x;          // 0..255
    const int ty   = tx >> 4;               // 0..15 -> 8 rows each
    const int txx  = tx & 15;               // 0..15 -> 4 cols each
    const int brow = blockIdx.y * 128;
    const int bcol = blockIdx.x * 64;

    float acc[8][4];
    #pragma unroll
    for (int r = 0; r < 8; r++)
        #pragma unroll
        for (int c = 0; c < 4; c++) acc[r][c] = 0.f;

    for (int k0 = 0; k0 < K; k0 += 16) {
        // load A tile 128x16, transposed into As[k][m]
        #pragma unroll
        for (int i = 0; i < 2; i++) {
            int f  = tx * 2 + i;            // 0..511 float4s
            int r  = f >> 2;                // row 0..127
            int kq = (f & 3) * 4;           // k 0,4,8,12
            float4 a = *(const float4*)(A + (size_t)(brow + r) * K + k0 + kq);
            As[kq + 0][r] = a.x;
            As[kq + 1][r] = a.y;
            As[kq + 2][r] = a.z;
            As[kq + 3][r] = a.w;
        }
        // load B tile 16x64, natural layout
        {
            int kr = tx >> 4;               // 0..15
            int cq = (tx & 15) * 4;         // 0..60
            *(float4*)&Bs[kr][cq] =
                *(const float4*)(Bm + (size_t)(k0 + kr) * N + bcol + cq);
        }
        __syncthreads();

        #pragma unroll
        for (int kk = 0; kk < 16; kk++) {
            float a0[8], b0[4];
            *(float4*)&a0[0] = *(float4*)&As[kk][ty * 8];
            *(float4*)&a0[4] = *(float4*)&As[kk][ty * 8 + 4];
            *(float4*)&b0[0] = *(float4*)&Bs[kk][txx * 4];
            #pragma unroll
            for (int r = 0; r < 8; r++)
                #pragma unroll
                for (int c = 0; c < 4; c++)
                    acc[r][c] = fmaf(a0[r], b0[c], acc[r][c]);
        }
        __syncthreads();
    }

    // epilogue
    const int col = bcol + txx * 4;
    float4 bb = make_float4(0.f, 0.f, 0.f, 0.f);
    if (EPI >= 1) bb = *(const float4*)(bias + col);
    #pragma unroll
    for (int r = 0; r < 8; r++) {
        int row = brow + ty * 8 + r;
        float4 o;
        o.x = acc[r][0] + bb.x;
        o.y = acc[r][1] + bb.y;
        o.z = acc[r][2] + bb.z;
        o.w = acc[r][3] + bb.w;
        if (EPI == 1) {
            o.x = fmaxf(o.x, 0.f); o.y = fmaxf(o.y, 0.f);
            o.z = fmaxf(o.z, 0.f); o.w = fmaxf(o.w, 0.f);
        }
        if (EPI == 2) {
            float4 rr = *(const float4*)(res + (size_t)row * N + col);
            o.x += rr.x; o.y += rr.y; o.z += rr.z; o.w += rr.w;
        }
        *(float4*)(Cm + (size_t)row * N + col) = o;
    }
}

// ---------------- causal flash attention, fp32 ----------------
// grid: (T/64 q-tiles, B*H). block: 256 threads.
// Br = Bc = 64, HD = 64. Per thread: 4 rows x 4 cols.
// smem: Qt[64][64] (d-major), KtPs[64][64] (K^T, reused for P^T), Vs[64][64].
__global__ void attn_kernel(const float* __restrict__ q,
                            const float* __restrict__ k,
                            const float* __restrict__ v,
                            float* __restrict__ o) {
    __shared__ float Qt[64][64];    // [d][row]
    __shared__ float KtPs[64][64];  // phase 1: [d][key]; phase 2: [key][row]
    __shared__ float Vs[64][64];    // [key][d]

    const int tx  = threadIdx.x;
    const int ty  = tx >> 4;        // 0..15 -> rows ty*4..+3
    const int txx = tx & 15;        // 0..15 -> cols txx*4..+3
    const int bh  = blockIdx.y;
    const int b   = bh >> 4;
    const int h   = bh & 15;
    const int t0  = blockIdx.x * 64;
    const size_t base = (size_t)b * T_ * C_ + (size_t)h * HD_;

    // load Q tile transposed: thread handles row tx>>2, dims (tx&3)*16 .. +15
    {
        int r  = tx >> 2;
        int d0 = (tx & 3) * 16;
        const float* src = q + base + (size_t)(t0 + r) * C_ + d0;
        #pragma unroll
        for (int i = 0; i < 16; i += 4) {
            float4 a = *(const float4*)(src + i);
            Qt[d0 + i + 0][r] = a.x;
            Qt[d0 + i + 1][r] = a.y;
            Qt[d0 + i + 2][r] = a.z;
            Qt[d0 + i + 3][r] = a.w;
        }
    }

    float m[4], l[4], acc[4][4];
    #pragma unroll
    for (int r = 0; r < 4; r++) {
        m[r] = -1e30f; l[r] = 0.f;
        #pragma unroll
        for (int c = 0; c < 4; c++) acc[r][c] = 0.f;
    }

    const int nTiles = blockIdx.x + 1;   // causal: only tiles <= diagonal
    for (int j = 0; j < nTiles; j++) {
        const int kt0 = j * 64;
        __syncthreads();   // previous iteration done with KtPs / Vs (also covers Qt fill on j=0)

        // load K tile transposed + V tile natural
        {
            int r  = tx >> 2;
            int d0 = (tx & 3) * 16;
            const float* ksrc = k + base + (size_t)(kt0 + r) * C_ + d0;
            const float* vsrc = v + base + (size_t)(kt0 + r) * C_ + d0;
            #pragma unroll
            for (int i = 0; i < 16; i += 4) {
                float4 a = *(const float4*)(ksrc + i);
                KtPs[d0 + i + 0][r] = a.x;
                KtPs[d0 + i + 1][r] = a.y;
                KtPs[d0 + i + 2][r] = a.z;
                KtPs[d0 + i + 3][r] = a.w;
                *(float4*)&Vs[r][d0 + i] = *(const float4*)(vsrc + i);
            }
        }
        __syncthreads();

        // S = Q @ K^T (4x4 per thread)
        float s[4][4];
        #pragma unroll
        for (int r = 0; r < 4; r++)
            #pragma unroll
            for (int c = 0; c < 4; c++) s[r][c] = 0.f;
        #pragma unroll 4
        for (int d = 0; d < 64; d++) {
            float qr[4], kc[4];
            *(float4*)qr = *(float4*)&Qt[d][ty * 4];
            *(float4*)kc = *(float4*)&KtPs[d][txx * 4];
            #pragma unroll
            for (int r = 0; r < 4; r++)
                #pragma unroll
                for (int c = 0; c < 4; c++)
                    s[r][c] = fmaf(qr[r], kc[c], s[r][c]);
        }

        // scale + causal mask (diagonal tile only)
        const float scale = 0.125f;   // 1/sqrt(64)
        #pragma unroll
        for (int r = 0; r < 4; r++)
            #pragma unroll
            for (int c = 0; c < 4; c++) {
                s[r][c] *= scale;
                if (j == blockIdx.x &&
                    (kt0 + txx * 4 + c) > (t0 + ty * 4 + r))
                    s[r][c] = -1e30f;
            }

        // online softmax (reduce over the 16 lanes sharing ty)
        float p[4][4], alpha[4];
        #pragma unroll
        for (int r = 0; r < 4; r++) {
            float rmax = fmaxf(fmaxf(s[r][0], s[r][1]), fmaxf(s[r][2], s[r][3]));
            #pragma unroll
            for (int off = 8; off >= 1; off >>= 1)
                rmax = fmaxf(rmax, __shfl_xor_sync(0xffffffffu, rmax, off));
            float mnew = fmaxf(m[r], rmax);
            alpha[r] = __expf(m[r] - mnew);
            float rsum = 0.f;
            #pragma unroll
            for (int c = 0; c < 4; c++) {
                p[r][c] = __expf(s[r][c] - mnew);
                rsum += p[r][c];
            }
            #pragma unroll
            for (int off = 8; off >= 1; off >>= 1)
                rsum += __shfl_xor_sync(0xffffffffu, rsum, off);
            l[r] = l[r] * alpha[r] + rsum;
            m[r] = mnew;
            #pragma unroll
            for (int c = 0; c < 4; c++) acc[r][c] *= alpha[r];
        }

        __syncthreads();   // everyone done reading KtPs as K^T

        // write P transposed into KtPs: [key][row]
        #pragma unroll
        for (int r = 0; r < 4; r++)
            #pragma unroll
            for (int c = 0; c < 4; c++)
                KtPs[txx * 4 + c][ty * 4 + r] = p[r][c];
        __syncthreads();

        // O += P @ V
        #pragma unroll 4
        for (int kk = 0; kk < 64; kk++) {
            float pr[4], vc[4];
            *(float4*)pr = *(float4*)&KtPs[kk][ty * 4];
            *(float4*)vc = *(float4*)&Vs[kk][txx * 4];
            #pragma unroll
            for (int r = 0; r < 4; r++)
                #pragma unroll
                for (int c = 0; c < 4; c++)
                    acc[r][c] = fmaf(pr[r], vc[c], acc[r][c]);
        }
    }

    // normalize and store
    #pragma unroll
    for (int r = 0; r < 4; r++) {
        float inv = 1.f / l[r];
        int row = t0 + ty * 4 + r;
        float4 out;
        out.x = acc[r][0] * inv;
        out.y = acc[r][1] * inv;
        out.z = acc[r][2] * inv;
        out.w = acc[r][3] * inv;
        *(float4*)(o + base + (size_t)row * C_ + txx * 4) = out;
    }
}

// ---------------- launch ----------------
extern "C" void kernel_launch(void* const* d_in, const int* in_sizes, int n_in,
                              void* d_out, int out_size) {
    const float* x    = (const float*)d_in[0];
    const float* Wq   = (const float*)d_in[1];
    const float* Wk   = (const float*)d_in[2];
    const float* Wv   = (const float*)d_in[3];
    const float* Wo   = (const float*)d_in[4];
    const float* bo   = (const float*)d_in[5];
    const float* ln1g = (const float*)d_in[6];
    const float* ln1b = (const float*)d_in[7];
    const float* ln2g = (const float*)d_in[8];
    const float* ln2b = (const float*)d_in[9];
    const float* W1   = (const float*)d_in[10];
    const float* b1   = (const float*)d_in[11];
    const float* W2   = (const float*)d_in[12];
    const float* b2   = (const float*)d_in[13];
    float* out = (float*)d_out;

    float *h, *q, *k, *v, *att, *x2, *h2, *ff1;
    cudaGetSymbolAddress((void**)&h,   g_h);
    cudaGetSymbolAddress((void**)&q,   g_q);
    cudaGetSymbolAddress((void**)&k,   g_k);
    cudaGetSymbolAddress((void**)&v,   g_v);
    cudaGetSymbolAddress((void**)&att, g_att);
    cudaGetSymbolAddress((void**)&x2,  g_x2);
    cudaGetSymbolAddress((void**)&h2,  g_h2);
    cudaGetSymbolAddress((void**)&ff1, g_ff1);

    // 1. h = LN1(x)
    ln_kernel<<<NR, 256>>>(x, ln1g, ln1b, h);

    // 2. q,k,v = h @ {Wq,Wk,Wv}
    dim3 gP(C_ / 64, NR / 128);
    gemm_kernel<0><<<gP, 256>>>(h, Wq, nullptr, nullptr, q, NR, C_, C_);
    gemm_kernel<0><<<gP, 256>>>(h, Wk, nullptr, nullptr, k, NR, C_, C_);
    gemm_kernel<0><<<gP, 256>>>(h, Wv, nullptr, nullptr, v, NR, C_, C_);

    // 3. causal attention
    attn_kernel<<<dim3(T_ / 64, B_ * H_), 256>>>(q, k, v, att);

    // 4. x2 = x + att @ Wo + bo
    gemm_kernel<2><<<gP, 256>>>(att, Wo, bo, x, x2, NR, C_, C_);

    // 5. h2 = LN2(x2)
    ln_kernel<<<NR, 256>>>(x2, ln2g, ln2b, h2);

    // 6. ff1 = relu(h2 @ W1 + b1)
    gemm_kernel<1><<<dim3(FF / 64, NR / 128), 256>>>(h2, W1, b1, nullptr, ff1, NR, FF, C_);

    // 7. out = x2 + ff1 @ W2 + b2
    gemm_kernel<2><<<gP, 256>>>(ff1, W2, b2, x2, out, NR, C_, FF);
}

// round 2
// speedup vs baseline: 1.8798x; 1.8798x over previous
#include <cuda_runtime.h>
#include <cstdint>

// Problem constants
#define B_  2
#define T_  2048
#define C_  1024
#define H_  16
#define HD_ 64
#define NR  (B_*T_)          // 4096 rows
#define FF  (4*C_)           // 4096

// ---------------- scratch (no allocations allowed) ----------------
__device__ float g_h  [NR*C_];   // ln1 out
__device__ float g_q  [NR*C_];
__device__ float g_k  [NR*C_];
__device__ float g_v  [NR*C_];
__device__ float g_att[NR*C_];
__device__ float g_x2 [NR*C_];   // post-attention residual
__device__ float g_h2 [NR*C_];   // ln2 out
__device__ float g_ff1[NR*FF];   // relu(h2@W1+b1)

// ---------------- small helpers ----------------
__device__ __forceinline__ uint32_t cvt_tf32(float x) {
    uint32_t r;
    asm("cvt.rna.tf32.f32 %0, %1;" : "=r"(r) : "f"(x));
    return r;
}
__device__ __forceinline__ uint32_t smem_u32(const void* p) {
    uint32_t a;
    asm("{ .reg .u64 t; cvta.to.shared.u64 t, %1; cvt.u32.u64 %0, t; }"
        : "=r"(a) : "l"(p));
    return a;
}
__device__ __forceinline__ void cp_async16(uint32_t s, const void* g) {
    asm volatile("cp.async.cg.shared.global [%0], [%1], 16;" :: "r"(s), "l"(g));
}
__device__ __forceinline__ void cp_commit_wait() {
    asm volatile("cp.async.commit_group;");
    asm volatile("cp.async.wait_group 0;");
}

// ---------------- block reduction (256 threads) ----------------
__device__ __forceinline__ float block_sum256(float v) {
    __shared__ float red[8];
    #pragma unroll
    for (int o = 16; o; o >>= 1) v += __shfl_xor_sync(0xffffffffu, v, o);
    __syncthreads();
    if ((threadIdx.x & 31) == 0) red[threadIdx.x >> 5] = v;
    __syncthreads();
    float s = 0.f;
    #pragma unroll
    for (int i = 0; i < 8; i++) s += red[i];
    return s;
}

// ---------------- LayerNorm: one block per row ----------------
__global__ void ln_kernel(const float* __restrict__ x,
                          const float* __restrict__ g,
                          const float* __restrict__ b,
                          float* __restrict__ out) {
    int row = blockIdx.x;
    const float4* xr = (const float4*)(x + (size_t)row * C_);
    float4 xa = xr[threadIdx.x];

    float s = xa.x + xa.y + xa.z + xa.w;
    float mu = block_sum256(s) * (1.0f / C_);

    float dx = xa.x - mu, dy = xa.y - mu, dz = xa.z - mu, dw = xa.w - mu;
    float sq = dx*dx + dy*dy + dz*dz + dw*dw;
    float var = block_sum256(sq) * (1.0f / C_);
    float rstd = rsqrtf(var + 1e-5f);

    float4 gg = ((const float4*)g)[threadIdx.x];
    float4 bb = ((const float4*)b)[threadIdx.x];
    float4 o;
    o.x = dx * rstd * gg.x + bb.x;
    o.y = dy * rstd * gg.y + bb.y;
    o.z = dz * rstd * gg.z + bb.z;
    o.w = dw * rstd * gg.w + bb.w;
    ((float4*)(out + (size_t)row * C_))[threadIdx.x] = o;
}

// ================= tf32 tensor-core GEMM ======================
// C[MxN] = A[MxK] @ B[KxN] (+bias)(+relu)(+residual)
// BM=128, BN=128, BK=32; 256 threads = 8 warps in 2x4 grid;
// warp tile 64x32 via m16n8k8 (4 mtiles x 4 ntiles, 4 ksteps).
// EPI: 0 = none, 1 = bias+relu, 2 = bias+residual
template <int EPI>
__device__ __forceinline__ void gemm_tc_body(
        const float* __restrict__ A, const float* __restrict__ Bm,
        const float* __restrict__ bias, const float* __restrict__ res,
        float* __restrict__ Cm, int M, int N, int K,
        int bx, int by) {
    __shared__ float As[128][36];   // [m][k], pad 4 -> LDS bank = 4g+t (bijective)
    __shared__ float Bs[32][136];   // [k][n], pad 8 -> LDS bank = 8t+g (bijective)

    const int tx   = threadIdx.x;
    const int warp = tx >> 5;
    const int lane = tx & 31;
    const int g    = lane >> 2;     // group id 0..7
    const int t    = lane & 3;      // thread-in-group 0..3
    const int wr   = (warp >> 2) * 64;  // warp row offset (0/64)
    const int wc   = (warp & 3) * 32;   // warp col offset (0/32/64/96)
    const int brow = by * 128;
    const int bcol = bx * 128;

    float acc[4][4][4];
    #pragma unroll
    for (int mt = 0; mt < 4; mt++)
        #pragma unroll
        for (int nt = 0; nt < 4; nt++)
            #pragma unroll
            for (int i = 0; i < 4; i++) acc[mt][nt][i] = 0.f;

    // cp.async mapping (constant per thread)
    // A tile: 1024 float4; idx -> row=idx>>3, k4=idx&7
    // B tile: 1024 float4; idx -> k=idx>>5, n4=idx&31
    const int ar[4]  = { (tx + 0*256) >> 3, (tx + 1*256) >> 3,
                         (tx + 2*256) >> 3, (tx + 3*256) >> 3 };
    const int ak4    = tx & 7;
    const int bk[4]  = { (tx + 0*256) >> 5, (tx + 1*256) >> 5,
                         (tx + 2*256) >> 5, (tx + 3*256) >> 5 };
    const int bn4    = tx & 31;

    for (int k0 = 0; k0 < K; k0 += 32) {
        #pragma unroll
        for (int i = 0; i < 4; i++)
            cp_async16(smem_u32(&As[ar[i]][ak4 * 4]),
                       A + (size_t)(brow + ar[i]) * K + k0 + ak4 * 4);
        #pragma unroll
        for (int i = 0; i < 4; i++)
            cp_async16(smem_u32(&Bs[bk[i]][bn4 * 4]),
                       Bm + (size_t)(k0 + bk[i]) * N + bcol + bn4 * 4);
        cp_commit_wait();
        __syncthreads();

        #pragma unroll
        for (int ks = 0; ks < 4; ks++) {
            uint32_t af[4][4], bf[4][2];
            #pragma unroll
            for (int mt = 0; mt < 4; mt++) {
                int m0 = wr + mt * 16 + g;
                af[mt][0] = cvt_tf32(As[m0    ][ks * 8 + t    ]);
                af[mt][1] = cvt_tf32(As[m0 + 8][ks * 8 + t    ]);
                af[mt][2] = cvt_tf32(As[m0    ][ks * 8 + t + 4]);
                af[mt][3] = cvt_tf32(As[m0 + 8][ks * 8 + t + 4]);
            }
            #pragma unroll
            for (int nt = 0; nt < 4; nt++) {
                int n0 = wc + nt * 8 + g;
                bf[nt][0] = cvt_tf32(Bs[ks * 8 + t    ][n0]);
                bf[nt][1] = cvt_tf32(Bs[ks * 8 + t + 4][n0]);
            }
            #pragma unroll
            for (int mt = 0; mt < 4; mt++)
                #pragma unroll
                for (int nt = 0; nt < 4; nt++) {
                    asm volatile(
                        "mma.sync.aligned.m16n8k8.row.col.f32.tf32.tf32.f32 "
                        "{%0,%1,%2,%3},{%4,%5,%6,%7},{%8,%9},{%0,%1,%2,%3};"
                        : "+f"(acc[mt][nt][0]), "+f"(acc[mt][nt][1]),
                          "+f"(acc[mt][nt][2]), "+f"(acc[mt][nt][3])
                        : "r"(af[mt][0]), "r"(af[mt][1]),
                          "r"(af[mt][2]), "r"(af[mt][3]),
                          "r"(bf[nt][0]), "r"(bf[nt][1]));
                }
        }
        __syncthreads();
    }

    // epilogue: c0=(g,2t) c1=(g,2t+1) c2=(g+8,2t) c3=(g+8,2t+1)
    #pragma unroll
    for (int mt = 0; mt < 4; mt++) {
        #pragma unroll
        for (int half = 0; half < 2; half++) {
            int row = brow + wr + mt * 16 + g + half * 8;
            #pragma unroll
            for (int nt = 0; nt < 4; nt++) {
                int col = bcol + wc + nt * 8 + 2 * t;
                float2 o;
                o.x = acc[mt][nt][half * 2 + 0];
                o.y = acc[mt][nt][half * 2 + 1];
                if (EPI >= 1) { o.x += bias[col]; o.y += bias[col + 1]; }
                if (EPI == 1) { o.x = fmaxf(o.x, 0.f); o.y = fmaxf(o.y, 0.f); }
                if (EPI == 2) {
                    float2 rr = *(const float2*)(res + (size_t)row * N + col);
                    o.x += rr.x; o.y += rr.y;
                }
                *(float2*)(Cm + (size_t)row * N + col) = o;
            }
        }
    }
}

template <int EPI>
__global__ void gemm_tc(const float* __restrict__ A,
                        const float* __restrict__ Bm,
                        const float* __restrict__ bias,
                        const float* __restrict__ res,
                        float* __restrict__ Cm,
                        int M, int N, int K) {
    gemm_tc_body<EPI>(A, Bm, bias, res, Cm, M, N, K, blockIdx.x, blockIdx.y);
}

// fused QKV: blockIdx.z selects weight/output
__global__ void gemm_tc_qkv(const float* __restrict__ A,
                            const float* __restrict__ W0,
                            const float* __restrict__ W1,
                            const float* __restrict__ W2,
                            float* __restrict__ C0,
                            float* __restrict__ C1,
                            float* __restrict__ C2,
                            int M, int N, int K) {
    const float* W = (blockIdx.z == 0) ? W0 : (blockIdx.z == 1) ? W1 : W2;
    float*       Cc = (blockIdx.z == 0) ? C0 : (blockIdx.z == 1) ? C1 : C2;
    gemm_tc_body<0>(A, W, nullptr, nullptr, Cc, M, N, K, blockIdx.x, blockIdx.y);
}

// ---------------- causal flash attention, fp32 ----------------
__global__ void attn_kernel(const float* __restrict__ q,
                            const float* __restrict__ k,
                            const float* __restrict__ v,
                            float* __restrict__ o) {
    __shared__ float Qt[64][64];    // [d][row]
    __shared__ float KtPs[64][64];  // phase 1: [d][key]; phase 2: [key][row]
    __shared__ float Vs[64][64];    // [key][d]

    const int tx  = threadIdx.x;
    const int ty  = tx >> 4;
    const int txx = tx & 15;
    const int bh  = blockIdx.y;
    const int b   = bh >> 4;
    const int h   = bh & 15;
    const int t0  = blockIdx.x * 64;
    const size_t base = (size_t)b * T_ * C_ + (size_t)h * HD_;

    {
        int r  = tx >> 2;
        int d0 = (tx & 3) * 16;
        const float* src = q + base + (size_t)(t0 + r) * C_ + d0;
        #pragma unroll
        for (int i = 0; i < 16; i += 4) {
            float4 a = *(const float4*)(src + i);
            Qt[d0 + i + 0][r] = a.x;
            Qt[d0 + i + 1][r] = a.y;
            Qt[d0 + i + 2][r] = a.z;
            Qt[d0 + i + 3][r] = a.w;
        }
    }

    float m[4], l[4], acc[4][4];
    #pragma unroll
    for (int r = 0; r < 4; r++) {
        m[r] = -1e30f; l[r] = 0.f;
        #pragma unroll
        for (int c = 0; c < 4; c++) acc[r][c] = 0.f;
    }

    const int nTiles = blockIdx.x + 1;
    for (int j = 0; j < nTiles; j++) {
        const int kt0 = j * 64;
        __syncthreads();

        {
            int r  = tx >> 2;
            int d0 = (tx & 3) * 16;
            const float* ksrc = k + base + (size_t)(kt0 + r) * C_ + d0;
            const float* vsrc = v + base + (size_t)(kt0 + r) * C_ + d0;
            #pragma unroll
            for (int i = 0; i < 16; i += 4) {
                float4 a = *(const float4*)(ksrc + i);
                KtPs[d0 + i + 0][r] = a.x;
                KtPs[d0 + i + 1][r] = a.y;
                KtPs[d0 + i + 2][r] = a.z;
                KtPs[d0 + i + 3][r] = a.w;
                *(float4*)&Vs[r][d0 + i] = *(const float4*)(vsrc + i);
            }
        }
        __syncthreads();

        float s[4][4];
        #pragma unroll
        for (int r = 0; r < 4; r++)
            #pragma unroll
            for (int c = 0; c < 4; c++) s[r][c] = 0.f;
        #pragma unroll 4
        for (int d = 0; d < 64; d++) {
            float qr[4], kc[4];
            *(float4*)qr = *(float4*)&Qt[d][ty * 4];
            *(float4*)kc = *(float4*)&KtPs[d][txx * 4];
            #pragma unroll
            for (int r = 0; r < 4; r++)
                #pragma unroll
                for (int c = 0; c < 4; c++)
                    s[r][c] = fmaf(qr[r], kc[c], s[r][c]);
        }

        const float scale = 0.125f;
        #pragma unroll
        for (int r = 0; r < 4; r++)
            #pragma unroll
            for (int c = 0; c < 4; c++) {
                s[r][c] *= scale;
                if (j == blockIdx.x &&
                    (kt0 + txx * 4 + c) > (t0 + ty * 4 + r))
                    s[r][c] = -1e30f;
            }

        float p[4][4], alpha[4];
        #pragma unroll
        for (int r = 0; r < 4; r++) {
            float rmax = fmaxf(fmaxf(s[r][0], s[r][1]), fmaxf(s[r][2], s[r][3]));
            #pragma unroll
            for (int off = 8; off >= 1; off >>= 1)
                rmax = fmaxf(rmax, __shfl_xor_sync(0xffffffffu, rmax, off));
            float mnew = fmaxf(m[r], rmax);
            alpha[r] = __expf(m[r] - mnew);
            float rsum = 0.f;
            #pragma unroll
            for (int c = 0; c < 4; c++) {
                p[r][c] = __expf(s[r][c] - mnew);
                rsum += p[r][c];
            }
            #pragma unroll
            for (int off = 8; off >= 1; off >>= 1)
                rsum += __shfl_xor_sync(0xffffffffu, rsum, off);
            l[r] = l[r] * alpha[r] + rsum;
            m[r] = mnew;
            #pragma unroll
            for (int c = 0; c < 4; c++) acc[r][c] *= alpha[r];
        }

        __syncthreads();

        #pragma unroll
        for (int r = 0; r < 4; r++)
            #pragma unroll
            for (int c = 0; c < 4; c++)
                KtPs[txx * 4 + c][ty * 4 + r] = p[r][c];
        __syncthreads();

        #pragma unroll 4
        for (int kk = 0; kk < 64; kk++) {
            float pr[4], vc[4];
            *(float4*)pr = *(float4*)&KtPs[kk][ty * 4];
            *(float4*)vc = *(float4*)&Vs[kk][txx * 4];
            #pragma unroll
            for (int r = 0; r < 4; r++)
                #pragma unroll
                for (int c = 0; c < 4; c++)
                    acc[r][c] = fmaf(pr[r], vc[c], acc[r][c]);
        }
    }

    #pragma unroll
    for (int r = 0; r < 4; r++) {
        float inv = 1.f / l[r];
        int row = t0 + ty * 4 + r;
        float4 out;
        out.x = acc[r][0] * inv;
        out.y = acc[r][1] * inv;
        out.z = acc[r][2] * inv;
        out.w = acc[r][3] * inv;
        *(float4*)(o + base + (size_t)row * C_ + txx * 4) = out;
    }
}

// ---------------- launch ----------------
extern "C" void kernel_launch(void* const* d_in, const int* in_sizes, int n_in,
                              void* d_out, int out_size) {
    const float* x    = (const float*)d_in[0];
    const float* Wq   = (const float*)d_in[1];
    const float* Wk   = (const float*)d_in[2];
    const float* Wv   = (const float*)d_in[3];
    const float* Wo   = (const float*)d_in[4];
    const float* bo   = (const float*)d_in[5];
    const float* ln1g = (const float*)d_in[6];
    const float* ln1b = (const float*)d_in[7];
    const float* ln2g = (const float*)d_in[8];
    const float* ln2b = (const float*)d_in[9];
    const float* W1   = (const float*)d_in[10];
    const float* b1   = (const float*)d_in[11];
    const float* W2   = (const float*)d_in[12];
    const float* b2   = (const float*)d_in[13];
    float* out = (float*)d_out;

    float *h, *q, *k, *v, *att, *x2, *h2, *ff1;
    cudaGetSymbolAddress((void**)&h,   g_h);
    cudaGetSymbolAddress((void**)&q,   g_q);
    cudaGetSymbolAddress((void**)&k,   g_k);
    cudaGetSymbolAddress((void**)&v,   g_v);
    cudaGetSymbolAddress((void**)&att, g_att);
    cudaGetSymbolAddress((void**)&x2,  g_x2);
    cudaGetSymbolAddress((void**)&h2,  g_h2);
    cudaGetSymbolAddress((void**)&ff1, g_ff1);

    // 1. h = LN1(x)
    ln_kernel<<<NR, 256>>>(x, ln1g, ln1b, h);

    // 2. q,k,v = h @ {Wq,Wk,Wv}  (fused over blockIdx.z)
    gemm_tc_qkv<<<dim3(C_ / 128, NR / 128, 3), 256>>>(
        h, Wq, Wk, Wv, q, k, v, NR, C_, C_);

    // 3. causal attention
    attn_kernel<<<dim3(T_ / 64, B_ * H_), 256>>>(q, k, v, att);

    // 4. x2 = x + att @ Wo + bo
    gemm_tc<2><<<dim3(C_ / 128, NR / 128), 256>>>(att, Wo, bo, x, x2, NR, C_, C_);

    // 5. h2 = LN2(x2)
    ln_kernel<<<NR, 256>>>(x2, ln2g, ln2b, h2);

    // 6. ff1 = relu(h2 @ W1 + b1)
    gemm_tc<1><<<dim3(FF / 128, NR / 128), 256>>>(h2, W1, b1, nullptr, ff1, NR, FF, C_);

    // 7. out = x2 + ff1 @ W2 + b2
    gemm_tc<2><<<dim3(C_ / 128, NR / 128), 256>>>(ff1, W2, b2, x2, out, NR, C_, FF);
}

// round 3
// speedup vs baseline: 2.2722x; 1.2087x over previous
#include <cuda_runtime.h>
#include <cstdint>

// Problem constants
#define B_  2
#define T_  2048
#define C_  1024
#define H_  16
#define HD_ 64
#define NR  (B_*T_)          // 4096 rows
#define FF  (4*C_)           // 4096

// ---------------- scratch (no allocations allowed) ----------------
__device__ float g_h  [NR*C_];   // ln1 out
__device__ float g_q  [NR*C_];
__device__ float g_k  [NR*C_];
__device__ float g_v  [NR*C_];
__device__ float g_att[NR*C_];
__device__ float g_x2 [NR*C_];   // post-attention residual
__device__ float g_h2 [NR*C_];   // ln2 out
__device__ float g_ff1[NR*FF];   // relu(h2@W1+b1)

// ---------------- small helpers ----------------
__device__ __forceinline__ uint32_t cvt_tf32(float x) {
    uint32_t r;
    asm("cvt.rna.tf32.f32 %0, %1;" : "=r"(r) : "f"(x));
    return r;
}
__device__ __forceinline__ uint32_t smem_u32(const void* p) {
    uint32_t a;
    asm("{ .reg .u64 t; cvta.to.shared.u64 t, %1; cvt.u32.u64 %0, t; }"
        : "=r"(a) : "l"(p));
    return a;
}
__device__ __forceinline__ void cp_async16(uint32_t s, const void* g) {
    asm volatile("cp.async.cg.shared.global [%0], [%1], 16;" :: "r"(s), "l"(g));
}
__device__ __forceinline__ void cp_commit() {
    asm volatile("cp.async.commit_group;");
}
__device__ __forceinline__ void cp_wait0() {
    asm volatile("cp.async.wait_group 0;");
}
__device__ __forceinline__ void cp_wait1() {
    asm volatile("cp.async.wait_group 1;");
}

// ---------------- block reduction (256 threads) ----------------
__device__ __forceinline__ float block_sum256(float v) {
    __shared__ float red[8];
    #pragma unroll
    for (int o = 16; o; o >>= 1) v += __shfl_xor_sync(0xffffffffu, v, o);
    __syncthreads();
    if ((threadIdx.x & 31) == 0) red[threadIdx.x >> 5] = v;
    __syncthreads();
    float s = 0.f;
    #pragma unroll
    for (int i = 0; i < 8; i++) s += red[i];
    return s;
}

// ---------------- LayerNorm: one block per row ----------------
__global__ void ln_kernel(const float* __restrict__ x,
                          const float* __restrict__ g,
                          const float* __restrict__ b,
                          float* __restrict__ out) {
    int row = blockIdx.x;
    const float4* xr = (const float4*)(x + (size_t)row * C_);
    float4 xa = xr[threadIdx.x];

    float s = xa.x + xa.y + xa.z + xa.w;
    float mu = block_sum256(s) * (1.0f / C_);

    float dx = xa.x - mu, dy = xa.y - mu, dz = xa.z - mu, dw = xa.w - mu;
    float sq = dx*dx + dy*dy + dz*dz + dw*dw;
    float var = block_sum256(sq) * (1.0f / C_);
    float rstd = rsqrtf(var + 1e-5f);

    float4 gg = ((const float4*)g)[threadIdx.x];
    float4 bb = ((const float4*)b)[threadIdx.x];
    float4 o;
    o.x = dx * rstd * gg.x + bb.x;
    o.y = dy * rstd * gg.y + bb.y;
    o.z = dz * rstd * gg.z + bb.z;
    o.w = dw * rstd * gg.w + bb.w;
    ((float4*)(out + (size_t)row * C_))[threadIdx.x] = o;
}

// ================= tf32 tensor-core GEMM (2-stage pipelined) =============
// C[MxN] = A[MxK] @ B[KxN] (+bias)(+relu)(+residual)
// BM=128, BN=128, BK=32; 256 threads = 8 warps (2x4); warp tile 64x32.
// Double-buffered smem in dynamic shared memory:
//   As: 2 stages of [128][36]  (pad 4: LDS bank = 4g+t, bijective per warp)
//   Bs: 2 stages of [32][136]  (pad 8: LDS bank = 8t+g, bijective per warp)
#define AS_STRIDE (128*36)
#define BS_STRIDE (32*136)
#define GEMM_SMEM_BYTES ((2*AS_STRIDE + 2*BS_STRIDE) * 4)

template <int EPI>
__device__ __forceinline__ void gemm_tc_body(
        const float* __restrict__ A, const float* __restrict__ Bm,
        const float* __restrict__ bias, const float* __restrict__ res,
        float* __restrict__ Cm, int M, int N, int K,
        int bx, int by) {
    extern __shared__ float smem[];
    float* AsBase = smem;                     // 2 * AS_STRIDE
    float* BsBase = smem + 2 * AS_STRIDE;     // 2 * BS_STRIDE

    const int tx   = threadIdx.x;
    const int warp = tx >> 5;
    const int lane = tx & 31;
    const int g    = lane >> 2;
    const int t    = lane & 3;
    const int wr   = (warp >> 2) * 64;
    const int wc   = (warp & 3) * 32;
    const int brow = by * 128;
    const int bcol = bx * 128;

    float acc[4][4][4];
    #pragma unroll
    for (int mt = 0; mt < 4; mt++)
        #pragma unroll
        for (int nt = 0; nt < 4; nt++)
            #pragma unroll
            for (int i = 0; i < 4; i++) acc[mt][nt][i] = 0.f;

    // cp.async mapping (constant per thread)
    const int ar0 = tx >> 3;           // A rows: ar0 + 32*i
    const int ak4 = tx & 7;
    const int bk0 = tx >> 5;           // B k-rows: bk0 + 8*i
    const int bn4 = tx & 31;

    const float* Ag = A + (size_t)(brow) * K + ak4 * 4;
    const float* Bg = Bm + (size_t)bk0 * N + bcol + bn4 * 4;

    // issue loads of k-tile kt into stage s
    auto issue = [&](int kt, int s) {
        float* As = AsBase + s * AS_STRIDE;
        float* Bs = BsBase + s * BS_STRIDE;
        const float* ag = Ag + kt * 32;
        const float* bg = Bg + (size_t)kt * 32 * N;
        #pragma unroll
        for (int i = 0; i < 4; i++) {
            int r = ar0 + 32 * i;
            cp_async16(smem_u32(As + r * 36 + ak4 * 4), ag + (size_t)r * K);
        }
        #pragma unroll
        for (int i = 0; i < 4; i++) {
            int kr = bk0 + 8 * i;
            cp_async16(smem_u32(Bs + kr * 136 + bn4 * 4), bg + (size_t)(8 * i) * N);
        }
        cp_commit();
    };

    const int ntiles = K >> 5;
    issue(0, 0);

    for (int kt = 0; kt < ntiles; kt++) {
        const int buf = kt & 1;
        const bool more = (kt + 1 < ntiles);
        if (more) issue(kt + 1, buf ^ 1);
        if (more) cp_wait1(); else cp_wait0();
        __syncthreads();

        const float* As = AsBase + buf * AS_STRIDE;
        const float* Bs = BsBase + buf * BS_STRIDE;

        #pragma unroll
        for (int ks = 0; ks < 4; ks++) {
            uint32_t af[4][4], bf[4][2];
            #pragma unroll
            for (int mt = 0; mt < 4; mt++) {
                int m0 = wr + mt * 16 + g;
                af[mt][0] = cvt_tf32(As[(m0    ) * 36 + ks * 8 + t    ]);
                af[mt][1] = cvt_tf32(As[(m0 + 8) * 36 + ks * 8 + t    ]);
                af[mt][2] = cvt_tf32(As[(m0    ) * 36 + ks * 8 + t + 4]);
                af[mt][3] = cvt_tf32(As[(m0 + 8) * 36 + ks * 8 + t + 4]);
            }
            #pragma unroll
            for (int nt = 0; nt < 4; nt++) {
                int n0 = wc + nt * 8 + g;
                bf[nt][0] = cvt_tf32(Bs[(ks * 8 + t    ) * 136 + n0]);
                bf[nt][1] = cvt_tf32(Bs[(ks * 8 + t + 4) * 136 + n0]);
            }
            #pragma unroll
            for (int mt = 0; mt < 4; mt++)
                #pragma unroll
                for (int nt = 0; nt < 4; nt++) {
                    asm volatile(
                        "mma.sync.aligned.m16n8k8.row.col.f32.tf32.tf32.f32 "
                        "{%0,%1,%2,%3},{%4,%5,%6,%7},{%8,%9},{%0,%1,%2,%3};"
                        : "+f"(acc[mt][nt][0]), "+f"(acc[mt][nt][1]),
                          "+f"(acc[mt][nt][2]), "+f"(acc[mt][nt][3])
                        : "r"(af[mt][0]), "r"(af[mt][1]),
                          "r"(af[mt][2]), "r"(af[mt][3]),
                          "r"(bf[nt][0]), "r"(bf[nt][1]));
                }
        }
        __syncthreads();   // all done reading buf before it is refilled
    }

    // epilogue: c0=(g,2t) c1=(g,2t+1) c2=(g+8,2t) c3=(g+8,2t+1)
    #pragma unroll
    for (int mt = 0; mt < 4; mt++) {
        #pragma unroll
        for (int half = 0; half < 2; half++) {
            int row = brow + wr + mt * 16 + g + half * 8;
            #pragma unroll
            for (int nt = 0; nt < 4; nt++) {
                int col = bcol + wc + nt * 8 + 2 * t;
                float2 o;
                o.x = acc[mt][nt][half * 2 + 0];
                o.y = acc[mt][nt][half * 2 + 1];
                if (EPI >= 1) { o.x += bias[col]; o.y += bias[col + 1]; }
                if (EPI == 1) { o.x = fmaxf(o.x, 0.f); o.y = fmaxf(o.y, 0.f); }
                if (EPI == 2) {
                    float2 rr = *(const float2*)(res + (size_t)row * N + col);
                    o.x += rr.x; o.y += rr.y;
                }
                *(float2*)(Cm + (size_t)row * N + col) = o;
            }
        }
    }
}

template <int EPI>
__global__ void __launch_bounds__(256)
gemm_tc(const float* __restrict__ A,
        const float* __restrict__ Bm,
        const float* __restrict__ bias,
        const float* __restrict__ res,
        float* __restrict__ Cm,
        int M, int N, int K) {
    gemm_tc_body<EPI>(A, Bm, bias, res, Cm, M, N, K, blockIdx.x, blockIdx.y);
}

// fused QKV: blockIdx.z selects weight/output
__global__ void __launch_bounds__(256)
gemm_tc_qkv(const float* __restrict__ A,
            const float* __restrict__ W0,
            const float* __restrict__ W1,
            const float* __restrict__ W2,
            float* __restrict__ C0,
            float* __restrict__ C1,
            float* __restrict__ C2,
            int M, int N, int K) {
    const float* W = (blockIdx.z == 0) ? W0 : (blockIdx.z == 1) ? W1 : W2;
    float*       Cc = (blockIdx.z == 0) ? C0 : (blockIdx.z == 1) ? C1 : C2;
    gemm_tc_body<0>(A, W, nullptr, nullptr, Cc, M, N, K, blockIdx.x, blockIdx.y);
}

// ---------------- causal flash attention, fp32 ----------------
__global__ void attn_kernel(const float* __restrict__ q,
                            const float* __restrict__ k,
                            const float* __restrict__ v,
                            float* __restrict__ o) {
    __shared__ float Qt[64][64];    // [d][row]
    __shared__ float KtPs[64][64];  // phase 1: [d][key]; phase 2: [key][row]
    __shared__ float Vs[64][64];    // [key][d]

    const int tx  = threadIdx.x;
    const int ty  = tx >> 4;
    const int txx = tx & 15;
    const int bh  = blockIdx.y;
    const int b   = bh >> 4;
    const int h   = bh & 15;
    const int t0  = blockIdx.x * 64;
    const size_t base = (size_t)b * T_ * C_ + (size_t)h * HD_;

    {
        int r  = tx >> 2;
        int d0 = (tx & 3) * 16;
        const float* src = q + base + (size_t)(t0 + r) * C_ + d0;
        #pragma unroll
        for (int i = 0; i < 16; i += 4) {
            float4 a = *(const float4*)(src + i);
            Qt[d0 + i + 0][r] = a.x;
            Qt[d0 + i + 1][r] = a.y;
            Qt[d0 + i + 2][r] = a.z;
            Qt[d0 + i + 3][r] = a.w;
        }
    }

    float m[4], l[4], acc[4][4];
    #pragma unroll
    for (int r = 0; r < 4; r++) {
        m[r] = -1e30f; l[r] = 0.f;
        #pragma unroll
        for (int c = 0; c < 4; c++) acc[r][c] = 0.f;
    }

    const int nTiles = blockIdx.x + 1;
    for (int j = 0; j < nTiles; j++) {
        const int kt0 = j * 64;
        __syncthreads();

        {
            int r  = tx >> 2;
            int d0 = (tx & 3) * 16;
            const float* ksrc = k + base + (size_t)(kt0 + r) * C_ + d0;
            const float* vsrc = v + base + (size_t)(kt0 + r) * C_ + d0;
            #pragma unroll
            for (int i = 0; i < 16; i += 4) {
                float4 a = *(const float4*)(ksrc + i);
                KtPs[d0 + i + 0][r] = a.x;
                KtPs[d0 + i + 1][r] = a.y;
                KtPs[d0 + i + 2][r] = a.z;
                KtPs[d0 + i + 3][r] = a.w;
                *(float4*)&Vs[r][d0 + i] = *(const float4*)(vsrc + i);
            }
        }
        __syncthreads();

        float s[4][4];
        #pragma unroll
        for (int r = 0; r < 4; r++)
            #pragma unroll
            for (int c = 0; c < 4; c++) s[r][c] = 0.f;
        #pragma unroll 4
        for (int d = 0; d < 64; d++) {
            float qr[4], kc[4];
            *(float4*)qr = *(float4*)&Qt[d][ty * 4];
            *(float4*)kc = *(float4*)&KtPs[d][txx * 4];
            #pragma unroll
            for (int r = 0; r < 4; r++)
                #pragma unroll
                for (int c = 0; c < 4; c++)
                    s[r][c] = fmaf(qr[r], kc[c], s[r][c]);
        }

        const float scale = 0.125f;
        #pragma unroll
        for (int r = 0; r < 4; r++)
            #pragma unroll
            for (int c = 0; c < 4; c++) {
                s[r][c] *= scale;
                if (j == blockIdx.x &&
                    (kt0 + txx * 4 + c) > (t0 + ty * 4 + r))
                    s[r][c] = -1e30f;
            }

        float p[4][4], alpha[4];
        #pragma unroll
        for (int r = 0; r < 4; r++) {
            float rmax = fmaxf(fmaxf(s[r][0], s[r][1]), fmaxf(s[r][2], s[r][3]));
            #pragma unroll
            for (int off = 8; off >= 1; off >>= 1)
                rmax = fmaxf(rmax, __shfl_xor_sync(0xffffffffu, rmax, off));
            float mnew = fmaxf(m[r], rmax);
            alpha[r] = __expf(m[r] - mnew);
            float rsum = 0.f;
            #pragma unroll
            for (int c = 0; c < 4; c++) {
                p[r][c] = __expf(s[r][c] - mnew);
                rsum += p[r][c];
            }
            #pragma unroll
            for (int off = 8; off >= 1; off >>= 1)
                rsum += __shfl_xor_sync(0xffffffffu, rsum, off);
            l[r] = l[r] * alpha[r] + rsum;
            m[r] = mnew;
            #pragma unroll
            for (int c = 0; c < 4; c++) acc[r][c] *= alpha[r];
        }

        __syncthreads();

        #pragma unroll
        for (int r = 0; r < 4; r++)
            #pragma unroll
            for (int c = 0; c < 4; c++)
                KtPs[txx * 4 + c][ty * 4 + r] = p[r][c];
        __syncthreads();

        #pragma unroll 4
        for (int kk = 0; kk < 64; kk++) {
            float pr[4], vc[4];
            *(float4*)pr = *(float4*)&KtPs[kk][ty * 4];
            *(float4*)vc = *(float4*)&Vs[kk][txx * 4];
            #pragma unroll
            for (int r = 0; r < 4; r++)
                #pragma unroll
                for (int c = 0; c < 4; c++)
                    acc[r][c] = fmaf(pr[r], vc[c], acc[r][c]);
        }
    }

    #pragma unroll
    for (int r = 0; r < 4; r++) {
        float inv = 1.f / l[r];
        int row = t0 + ty * 4 + r;
        float4 out;
        out.x = acc[r][0] * inv;
        out.y = acc[r][1] * inv;
        out.z = acc[r][2] * inv;
        out.w = acc[r][3] * inv;
        *(float4*)(o + base + (size_t)row * C_ + txx * 4) = out;
    }
}

// ---------------- launch ----------------
extern "C" void kernel_launch(void* const* d_in, const int* in_sizes, int n_in,
                              void* d_out, int out_size) {
    const float* x    = (const float*)d_in[0];
    const float* Wq   = (const float*)d_in[1];
    const float* Wk   = (const float*)d_in[2];
    const float* Wv   = (const float*)d_in[3];
    const float* Wo   = (const float*)d_in[4];
    const float* bo   = (const float*)d_in[5];
    const float* ln1g = (const float*)d_in[6];
    const float* ln1b = (const float*)d_in[7];
    const float* ln2g = (const float*)d_in[8];
    const float* ln2b = (const float*)d_in[9];
    const float* W1   = (const float*)d_in[10];
    const float* b1   = (const float*)d_in[11];
    const float* W2   = (const float*)d_in[12];
    const float* b2   = (const float*)d_in[13];
    float* out = (float*)d_out;

    float *h, *q, *k, *v, *att, *x2, *h2, *ff1;
    cudaGetSymbolAddress((void**)&h,   g_h);
    cudaGetSymbolAddress((void**)&q,   g_q);
    cudaGetSymbolAddress((void**)&k,   g_k);
    cudaGetSymbolAddress((void**)&v,   g_v);
    cudaGetSymbolAddress((void**)&att, g_att);
    cudaGetSymbolAddress((void**)&x2,  g_x2);
    cudaGetSymbolAddress((void**)&h2,  g_h2);
    cudaGetSymbolAddress((void**)&ff1, g_ff1);

    // raise dynamic smem limits (host-side attribute, not a stream op)
    static bool attr_done = false;
    if (!attr_done) {
        cudaFuncSetAttribute(gemm_tc<0>,  cudaFuncAttributeMaxDynamicSharedMemorySize, GEMM_SMEM_BYTES);
        cudaFuncSetAttribute(gemm_tc<1>,  cudaFuncAttributeMaxDynamicSharedMemorySize, GEMM_SMEM_BYTES);
        cudaFuncSetAttribute(gemm_tc<2>,  cudaFuncAttributeMaxDynamicSharedMemorySize, GEMM_SMEM_BYTES);
        cudaFuncSetAttribute(gemm_tc_qkv, cudaFuncAttributeMaxDynamicSharedMemorySize, GEMM_SMEM_BYTES);
        attr_done = true;
    }

    // 1. h = LN1(x)
    ln_kernel<<<NR, 256>>>(x, ln1g, ln1b, h);

    // 2. q,k,v = h @ {Wq,Wk,Wv}  (fused over blockIdx.z)
    gemm_tc_qkv<<<dim3(C_ / 128, NR / 128, 3), 256, GEMM_SMEM_BYTES>>>(
        h, Wq, Wk, Wv, q, k, v, NR, C_, C_);

    // 3. causal attention
    attn_kernel<<<dim3(T_ / 64, B_ * H_), 256>>>(q, k, v, att);

    // 4. x2 = x + att @ Wo + bo
    gemm_tc<2><<<dim3(C_ / 128, NR / 128), 256, GEMM_SMEM_BYTES>>>(att, Wo, bo, x, x2, NR, C_, C_);

    // 5. h2 = LN2(x2)
    ln_kernel<<<NR, 256>>>(x2, ln2g, ln2b, h2);

    // 6. ff1 = relu(h2 @ W1 + b1)
    gemm_tc<1><<<dim3(FF / 128, NR / 128), 256, GEMM_SMEM_BYTES>>>(h2, W1, b1, nullptr, ff1, NR, FF, C_);

    // 7. out = x2 + ff1 @ W2 + b2
    gemm_tc<2><<<dim3(C_ / 128, NR / 128), 256, GEMM_SMEM_BYTES>>>(ff1, W2, b2, x2, out, NR, C_, FF);
}

// round 4
// speedup vs baseline: 2.3480x; 1.0334x over previous
#include <cuda_runtime.h>
#include <cstdint>

// Problem constants
#define B_  2
#define T_  2048
#define C_  1024
#define H_  16
#define HD_ 64
#define NR  (B_*T_)          // 4096 rows
#define FF  (4*C_)           // 4096

// ---------------- scratch (no allocations allowed) ----------------
__device__ float g_h  [NR*C_];   // ln1 out (tf32-rounded)
__device__ float g_q  [NR*C_];
__device__ float g_k  [NR*C_];
__device__ float g_v  [NR*C_];
__device__ float g_att[NR*C_];   // attention out (tf32-rounded)
__device__ float g_x2 [NR*C_];   // post-attention residual
__device__ float g_h2 [NR*C_];   // ln2 out (tf32-rounded)
__device__ float g_ff1[NR*FF];   // relu(h2@W1+b1) (tf32-rounded)
// tf32-rounded weight copies
__device__ float g_wq [C_*C_];
__device__ float g_wk [C_*C_];
__device__ float g_wv [C_*C_];
__device__ float g_wo [C_*C_];
__device__ float g_w1 [C_*FF];
__device__ float g_w2 [FF*C_];

// ---------------- small helpers ----------------
__device__ __forceinline__ uint32_t cvt_tf32(float x) {
    uint32_t r;
    asm("cvt.rna.tf32.f32 %0, %1;" : "=r"(r) : "f"(x));
    return r;
}
__device__ __forceinline__ float round_tf32(float x) {
    return __uint_as_float(cvt_tf32(x));
}
__device__ __forceinline__ uint32_t smem_u32(const void* p) {
    uint32_t a;
    asm("{ .reg .u64 t; cvta.to.shared.u64 t, %1; cvt.u32.u64 %0, t; }"
        : "=r"(a) : "l"(p));
    return a;
}
__device__ __forceinline__ void cp_async16(uint32_t s, const void* g) {
    asm volatile("cp.async.cg.shared.global [%0], [%1], 16;" :: "r"(s), "l"(g));
}
__device__ __forceinline__ void cp_commit() {
    asm volatile("cp.async.commit_group;");
}
__device__ __forceinline__ void cp_wait1() {
    asm volatile("cp.async.wait_group 1;");
}

// ---------------- weight tf32 pre-rounding ----------------
__global__ void cvt_w_kernel(const float* __restrict__ s,
                             float* __restrict__ d, int n4) {
    int i = blockIdx.x * blockDim.x + threadIdx.x;
    if (i >= n4) return;
    float4 v = ((const float4*)s)[i];
    v.x = round_tf32(v.x); v.y = round_tf32(v.y);
    v.z = round_tf32(v.z); v.w = round_tf32(v.w);
    ((float4*)d)[i] = v;
}

// ---------------- block reduction (256 threads) ----------------
__device__ __forceinline__ float block_sum256(float v) {
    __shared__ float red[8];
    #pragma unroll
    for (int o = 16; o; o >>= 1) v += __shfl_xor_sync(0xffffffffu, v, o);
    __syncthreads();
    if ((threadIdx.x & 31) == 0) red[threadIdx.x >> 5] = v;
    __syncthreads();
    float s = 0.f;
    #pragma unroll
    for (int i = 0; i < 8; i++) s += red[i];
    return s;
}

// ---------------- LayerNorm: one block per row (output tf32-rounded) -----
__global__ void ln_kernel(const float* __restrict__ x,
                          const float* __restrict__ g,
                          const float* __restrict__ b,
                          float* __restrict__ out) {
    int row = blockIdx.x;
    const float4* xr = (const float4*)(x + (size_t)row * C_);
    float4 xa = xr[threadIdx.x];

    float s = xa.x + xa.y + xa.z + xa.w;
    float mu = block_sum256(s) * (1.0f / C_);

    float dx = xa.x - mu, dy = xa.y - mu, dz = xa.z - mu, dw = xa.w - mu;
    float sq = dx*dx + dy*dy + dz*dz + dw*dw;
    float var = block_sum256(sq) * (1.0f / C_);
    float rstd = rsqrtf(var + 1e-5f);

    float4 gg = ((const float4*)g)[threadIdx.x];
    float4 bb = ((const float4*)b)[threadIdx.x];
    float4 o;
    o.x = round_tf32(dx * rstd * gg.x + bb.x);
    o.y = round_tf32(dy * rstd * gg.y + bb.y);
    o.z = round_tf32(dz * rstd * gg.z + bb.z);
    o.w = round_tf32(dw * rstd * gg.w + bb.w);
    ((float4*)(out + (size_t)row * C_))[threadIdx.x] = o;
}

// ================= tf32 tensor-core GEMM (3-stage pipelined) =============
// C[MxN] = A[MxK] @ B[KxN] (+bias)(+relu)(+residual)
// Operands are PRE-ROUNDED to tf32 (raw fp32 bits fed to mma).
// BM=128, BN=128, BK=32; 256 threads = 8 warps (2x4); warp tile 64x32.
// 3 smem stages, ONE __syncthreads per k-tile:
//   iter kt: wait_group(1) -> sync -> issue(kt+2) -> compute(kt)
//   stage (kt+2)%3 was last read at iter kt-1; the iter-kt barrier protects it.
#define AS_STRIDE (128*36)   // pad 4: LDS bank = 4g+t (bijective per warp)
#define BS_STRIDE (32*136)   // pad 8: LDS bank = 8t+g (bijective per warp)
#define STAGE_STRIDE (AS_STRIDE + BS_STRIDE)
#define GEMM_SMEM_BYTES (3 * STAGE_STRIDE * 4)

template <int EPI, bool ROUND>
__device__ __forceinline__ void gemm_tc_body(
        const float* __restrict__ A, const float* __restrict__ Bm,
        const float* __restrict__ bias, const float* __restrict__ res,
        float* __restrict__ Cm, int M, int N, int K,
        int bx, int by) {
    extern __shared__ float smem[];

    const int tx   = threadIdx.x;
    const int warp = tx >> 5;
    const int lane = tx & 31;
    const int g    = lane >> 2;
    const int t    = lane & 3;
    const int wr   = (warp >> 2) * 64;
    const int wc   = (warp & 3) * 32;
    const int brow = by * 128;
    const int bcol = bx * 128;

    float acc[4][4][4];
    #pragma unroll
    for (int mt = 0; mt < 4; mt++)
        #pragma unroll
        for (int nt = 0; nt < 4; nt++)
            #pragma unroll
            for (int i = 0; i < 4; i++) acc[mt][nt][i] = 0.f;

    const int ar0 = tx >> 3;           // A rows: ar0 + 32*i
    const int ak4 = tx & 7;
    const int bk0 = tx >> 5;           // B k-rows: bk0 + 8*i
    const int bn4 = tx & 31;

    const float* Ag = A + (size_t)brow * K + ak4 * 4;
    const float* Bg = Bm + (size_t)bk0 * N + bcol + bn4 * 4;
    const int ntiles = K >> 5;

    auto issue = [&](int kt, int s) {
        if (kt < ntiles) {
            float* As = smem + s * STAGE_STRIDE;
            float* Bs = As + AS_STRIDE;
            const float* ag = Ag + kt * 32;
            const float* bg = Bg + (size_t)kt * 32 * N;
            #pragma unroll
            for (int i = 0; i < 4; i++) {
                int r = ar0 + 32 * i;
                cp_async16(smem_u32(As + r * 36 + ak4 * 4), ag + (size_t)r * K);
            }
            #pragma unroll
            for (int i = 0; i < 4; i++) {
                int kr = bk0 + 8 * i;
                cp_async16(smem_u32(Bs + kr * 136 + bn4 * 4), bg + (size_t)(8 * i) * N);
            }
        }
        cp_commit();   // always commit so wait_group counts stay aligned
    };

    issue(0, 0);
    issue(1, 1);

    int s_c = 0;   // compute stage
    int s_w = 2;   // write stage
    for (int kt = 0; kt < ntiles; kt++) {
        cp_wait1();
        __syncthreads();
        issue(kt + 2, s_w);

        const float* As = smem + s_c * STAGE_STRIDE;
        const float* Bs = As + AS_STRIDE;

        #pragma unroll
        for (int ks = 0; ks < 4; ks++) {
            uint32_t af[4][4], bf[4][2];
            #pragma unroll
            for (int mt = 0; mt < 4; mt++) {
                int m0 = wr + mt * 16 + g;
                af[mt][0] = __float_as_uint(As[(m0    ) * 36 + ks * 8 + t    ]);
                af[mt][1] = __float_as_uint(As[(m0 + 8) * 36 + ks * 8 + t    ]);
                af[mt][2] = __float_as_uint(As[(m0    ) * 36 + ks * 8 + t + 4]);
                af[mt][3] = __float_as_uint(As[(m0 + 8) * 36 + ks * 8 + t + 4]);
            }
            #pragma unroll
            for (int nt = 0; nt < 4; nt++) {
                int n0 = wc + nt * 8 + g;
                bf[nt][0] = __float_as_uint(Bs[(ks * 8 + t    ) * 136 + n0]);
                bf[nt][1] = __float_as_uint(Bs[(ks * 8 + t + 4) * 136 + n0]);
            }
            #pragma unroll
            for (int mt = 0; mt < 4; mt++)
                #pragma unroll
                for (int nt = 0; nt < 4; nt++) {
                    asm volatile(
                        "mma.sync.aligned.m16n8k8.row.col.f32.tf32.tf32.f32 "
                        "{%0,%1,%2,%3},{%4,%5,%6,%7},{%8,%9},{%0,%1,%2,%3};"
                        : "+f"(acc[mt][nt][0]), "+f"(acc[mt][nt][1]),
                          "+f"(acc[mt][nt][2]), "+f"(acc[mt][nt][3])
                        : "r"(af[mt][0]), "r"(af[mt][1]),
                          "r"(af[mt][2]), "r"(af[mt][3]),
                          "r"(bf[nt][0]), "r"(bf[nt][1]));
                }
        }
        s_c = (s_c == 2) ? 0 : s_c + 1;
        s_w = (s_w == 2) ? 0 : s_w + 1;
    }

    // epilogue: c0=(g,2t) c1=(g,2t+1) c2=(g+8,2t) c3=(g+8,2t+1)
    #pragma unroll
    for (int mt = 0; mt < 4; mt++) {
        #pragma unroll
        for (int half = 0; half < 2; half++) {
            int row = brow + wr + mt * 16 + g + half * 8;
            #pragma unroll
            for (int nt = 0; nt < 4; nt++) {
                int col = bcol + wc + nt * 8 + 2 * t;
                float2 o;
                o.x = acc[mt][nt][half * 2 + 0];
                o.y = acc[mt][nt][half * 2 + 1];
                if (EPI >= 1) { o.x += bias[col]; o.y += bias[col + 1]; }
                if (EPI == 1) { o.x = fmaxf(o.x, 0.f); o.y = fmaxf(o.y, 0.f); }
                if (EPI == 2) {
                    float2 rr = *(const float2*)(res + (size_t)row * N + col);
                    o.x += rr.x; o.y += rr.y;
                }
                if (ROUND) { o.x = round_tf32(o.x); o.y = round_tf32(o.y); }
                *(float2*)(Cm + (size_t)row * N + col) = o;
            }
        }
    }
}

template <int EPI, bool ROUND>
__global__ void __launch_bounds__(256, 2)
gemm_tc(const float* __restrict__ A,
        const float* __restrict__ Bm,
        const float* __restrict__ bias,
        const float* __restrict__ res,
        float* __restrict__ Cm,
        int M, int N, int K) {
    gemm_tc_body<EPI, ROUND>(A, Bm, bias, res, Cm, M, N, K, blockIdx.x, blockIdx.y);
}

// fused QKV: blockIdx.z selects weight/output
__global__ void __launch_bounds__(256, 2)
gemm_tc_qkv(const float* __restrict__ A,
            const float* __restrict__ W0,
            const float* __restrict__ W1,
            const float* __restrict__ W2,
            float* __restrict__ C0,
            float* __restrict__ C1,
            float* __restrict__ C2,
            int M, int N, int K) {
    const float* W = (blockIdx.z == 0) ? W0 : (blockIdx.z == 1) ? W1 : W2;
    float*       Cc = (blockIdx.z == 0) ? C0 : (blockIdx.z == 1) ? C1 : C2;
    gemm_tc_body<0, false>(A, W, nullptr, nullptr, Cc, M, N, K, blockIdx.x, blockIdx.y);
}

// ---------------- causal flash attention, fp32 (tf32-rounded output) -----
__global__ void attn_kernel(const float* __restrict__ q,
                            const float* __restrict__ k,
                            const float* __restrict__ v,
                            float* __restrict__ o) {
    __shared__ float Qt[64][64];    // [d][row]
    __shared__ float KtPs[64][64];  // phase 1: [d][key]; phase 2: [key][row]
    __shared__ float Vs[64][64];    // [key][d]

    const int tx  = threadIdx.x;
    const int ty  = tx >> 4;
    const int txx = tx & 15;
    const int bh  = blockIdx.y;
    const int b   = bh >> 4;
    const int h   = bh & 15;
    const int t0  = blockIdx.x * 64;
    const size_t base = (size_t)b * T_ * C_ + (size_t)h * HD_;

    {
        int r  = tx >> 2;
        int d0 = (tx & 3) * 16;
        const float* src = q + base + (size_t)(t0 + r) * C_ + d0;
        #pragma unroll
        for (int i = 0; i < 16; i += 4) {
            float4 a = *(const float4*)(src + i);
            Qt[d0 + i + 0][r] = a.x;
            Qt[d0 + i + 1][r] = a.y;
            Qt[d0 + i + 2][r] = a.z;
            Qt[d0 + i + 3][r] = a.w;
        }
    }

    float m[4], l[4], acc[4][4];
    #pragma unroll
    for (int r = 0; r < 4; r++) {
        m[r] = -1e30f; l[r] = 0.f;
        #pragma unroll
        for (int c = 0; c < 4; c++) acc[r][c] = 0.f;
    }

    const int nTiles = blockIdx.x + 1;
    for (int j = 0; j < nTiles; j++) {
        const int kt0 = j * 64;
        __syncthreads();

        {
            int r  = tx >> 2;
            int d0 = (tx & 3) * 16;
            const float* ksrc = k + base + (size_t)(kt0 + r) * C_ + d0;
            const float* vsrc = v + base + (size_t)(kt0 + r) * C_ + d0;
            #pragma unroll
            for (int i = 0; i < 16; i += 4) {
                float4 a = *(const float4*)(ksrc + i);
                KtPs[d0 + i + 0][r] = a.x;
                KtPs[d0 + i + 1][r] = a.y;
                KtPs[d0 + i + 2][r] = a.z;
                KtPs[d0 + i + 3][r] = a.w;
                *(float4*)&Vs[r][d0 + i] = *(const float4*)(vsrc + i);
            }
        }
        __syncthreads();

        float s[4][4];
        #pragma unroll
        for (int r = 0; r < 4; r++)
            #pragma unroll
            for (int c = 0; c < 4; c++) s[r][c] = 0.f;
        #pragma unroll 4
        for (int d = 0; d < 64; d++) {
            float qr[4], kc[4];
            *(float4*)qr = *(float4*)&Qt[d][ty * 4];
            *(float4*)kc = *(float4*)&KtPs[d][txx * 4];
            #pragma unroll
            for (int r = 0; r < 4; r++)
                #pragma unroll
                for (int c = 0; c < 4; c++)
                    s[r][c] = fmaf(qr[r], kc[c], s[r][c]);
        }

        const float scale = 0.125f;
        #pragma unroll
        for (int r = 0; r < 4; r++)
            #pragma unroll
            for (int c = 0; c < 4; c++) {
                s[r][c] *= scale;
                if (j == blockIdx.x &&
                    (kt0 + txx * 4 + c) > (t0 + ty * 4 + r))
                    s[r][c] = -1e30f;
            }

        float p[4][4], alpha[4];
        #pragma unroll
        for (int r = 0; r < 4; r++) {
            float rmax = fmaxf(fmaxf(s[r][0], s[r][1]), fmaxf(s[r][2], s[r][3]));
            #pragma unroll
            for (int off = 8; off >= 1; off >>= 1)
                rmax = fmaxf(rmax, __shfl_xor_sync(0xffffffffu, rmax, off));
            float mnew = fmaxf(m[r], rmax);
            alpha[r] = __expf(m[r] - mnew);
            float rsum = 0.f;
            #pragma unroll
            for (int c = 0; c < 4; c++) {
                p[r][c] = __expf(s[r][c] - mnew);
                rsum += p[r][c];
            }
            #pragma unroll
            for (int off = 8; off >= 1; off >>= 1)
                rsum += __shfl_xor_sync(0xffffffffu, rsum, off);
            l[r] = l[r] * alpha[r] + rsum;
            m[r] = mnew;
            #pragma unroll
            for (int c = 0; c < 4; c++) acc[r][c] *= alpha[r];
        }

        __syncthreads();

        #pragma unroll
        for (int r = 0; r < 4; r++)
            #pragma unroll
            for (int c = 0; c < 4; c++)
                KtPs[txx * 4 + c][ty * 4 + r] = p[r][c];
        __syncthreads();

        #pragma unroll 4
        for (int kk = 0; kk < 64; kk++) {
            float pr[4], vc[4];
            *(float4*)pr = *(float4*)&KtPs[kk][ty * 4];
            *(float4*)vc = *(float4*)&Vs[kk][txx * 4];
            #pragma unroll
            for (int r = 0; r < 4; r++)
                #pragma unroll
                for (int c = 0; c < 4; c++)
                    acc[r][c] = fmaf(pr[r], vc[c], acc[r][c]);
        }
    }

    #pragma unroll
    for (int r = 0; r < 4; r++) {
        float inv = 1.f / l[r];
        int row = t0 + ty * 4 + r;
        float4 out;
        out.x = round_tf32(acc[r][0] * inv);
        out.y = round_tf32(acc[r][1] * inv);
        out.z = round_tf32(acc[r][2] * inv);
        out.w = round_tf32(acc[r][3] * inv);
        *(float4*)(o + base + (size_t)row * C_ + txx * 4) = out;
    }
}

// ---------------- launch ----------------
extern "C" void kernel_launch(void* const* d_in, const int* in_sizes, int n_in,
                              void* d_out, int out_size) {
    const float* x    = (const float*)d_in[0];
    const float* Wq   = (const float*)d_in[1];
    const float* Wk   = (const float*)d_in[2];
    const float* Wv   = (const float*)d_in[3];
    const float* Wo   = (const float*)d_in[4];
    const float* bo   = (const float*)d_in[5];
    const float* ln1g = (const float*)d_in[6];
    const float* ln1b = (const float*)d_in[7];
    const float* ln2g = (const float*)d_in[8];
    const float* ln2b = (const float*)d_in[9];
    const float* W1   = (const float*)d_in[10];
    const float* b1   = (const float*)d_in[11];
    const float* W2   = (const float*)d_in[12];
    const float* b2   = (const float*)d_in[13];
    float* out = (float*)d_out;

    float *h, *q, *k, *v, *att, *x2, *h2, *ff1;
    float *wq, *wk, *wv, *wo, *w1, *w2;
    cudaGetSymbolAddress((void**)&h,   g_h);
    cudaGetSymbolAddress((void**)&q,   g_q);
    cudaGetSymbolAddress((void**)&k,   g_k);
    cudaGetSymbolAddress((void**)&v,   g_v);
    cudaGetSymbolAddress((void**)&att, g_att);
    cudaGetSymbolAddress((void**)&x2,  g_x2);
    cudaGetSymbolAddress((void**)&h2,  g_h2);
    cudaGetSymbolAddress((void**)&ff1, g_ff1);
    cudaGetSymbolAddress((void**)&wq,  g_wq);
    cudaGetSymbolAddress((void**)&wk,  g_wk);
    cudaGetSymbolAddress((void**)&wv,  g_wv);
    cudaGetSymbolAddress((void**)&wo,  g_wo);
    cudaGetSymbolAddress((void**)&w1,  g_w1);
    cudaGetSymbolAddress((void**)&w2,  g_w2);

    // raise dynamic smem limits (host-side attribute, idempotent, not a stream op)
    cudaFuncSetAttribute(gemm_tc<0,false>, cudaFuncAttributeMaxDynamicSharedMemorySize, GEMM_SMEM_BYTES);
    cudaFuncSetAttribute(gemm_tc<1,true>,  cudaFuncAttributeMaxDynamicSharedMemorySize, GEMM_SMEM_BYTES);
    cudaFuncSetAttribute(gemm_tc<2,false>, cudaFuncAttributeMaxDynamicSharedMemorySize, GEMM_SMEM_BYTES);
    cudaFuncSetAttribute(gemm_tc_qkv,      cudaFuncAttributeMaxDynamicSharedMemorySize, GEMM_SMEM_BYTES);

    // 0. pre-round weights to tf32 (stored as fp32 bits)
    const int CC4 = C_ * C_ / 4, CF4 = C_ * FF / 4;
    cvt_w_kernel<<<CC4 / 256, 256>>>(Wq, wq, CC4);
    cvt_w_kernel<<<CC4 / 256, 256>>>(Wk, wk, CC4);
    cvt_w_kernel<<<CC4 / 256, 256>>>(Wv, wv, CC4);
    cvt_w_kernel<<<CC4 / 256, 256>>>(Wo, wo, CC4);
    cvt_w_kernel<<<CF4 / 256, 256>>>(W1, w1, CF4);
    cvt_w_kernel<<<CF4 / 256, 256>>>(W2, w2, CF4);

    // 1. h = LN1(x)  (rounded)
    ln_kernel<<<NR, 256>>>(x, ln1g, ln1b, h);

    // 2. q,k,v = h @ {Wq,Wk,Wv}
    gemm_tc_qkv<<<dim3(C_ / 128, NR / 128, 3), 256, GEMM_SMEM_BYTES>>>(
        h, wq, wk, wv, q, k, v, NR, C_, C_);

    // 3. causal attention (output rounded)
    attn_kernel<<<dim3(T_ / 64, B_ * H_), 256>>>(q, k, v, att);

    // 4. x2 = x + att @ Wo + bo
    gemm_tc<2,false><<<dim3(C_ / 128, NR / 128), 256, GEMM_SMEM_BYTES>>>(att, wo, bo, x, x2, NR, C_, C_);

    // 5. h2 = LN2(x2)  (rounded)
    ln_kernel<<<NR, 256>>>(x2, ln2g, ln2b, h2);

    // 6. ff1 = relu(h2 @ W1 + b1)  (rounded)
    gemm_tc<1,true><<<dim3(FF / 128, NR / 128), 256, GEMM_SMEM_BYTES>>>(h2, w1, b1, nullptr, ff1, NR, FF, C_);

    // 7. out = x2 + ff1 @ W2 + b2
    gemm_tc<2,false><<<dim3(C_ / 128, NR / 128), 256, GEMM_SMEM_BYTES>>>(ff1, w2, b2, x2, out, NR, C_, FF);
}

// round 5
// speedup vs baseline: 4.0419x; 1.7214x over previous
#include <cuda_runtime.h>
#include <cstdint>

// Problem constants
#define B_  2
#define T_  2048
#define C_  1024
#define H_  16
#define HD_ 64
#define NR  (B_*T_)          // 4096 rows
#define FF  (4*C_)           // 4096

// ---------------- scratch (no allocations allowed) ----------------
__device__ float g_h  [NR*C_];   // ln1 out (tf32-rounded)
__device__ float g_q  [NR*C_];   // tf32-rounded
__device__ float g_k  [NR*C_];   // tf32-rounded
__device__ float g_v  [NR*C_];   // tf32-rounded
__device__ float g_att[NR*C_];   // attention out (tf32-rounded)
__device__ float g_x2 [NR*C_];   // post-attention residual
__device__ float g_h2 [NR*C_];   // ln2 out (tf32-rounded)
__device__ float g_ff1[NR*FF];   // relu(h2@W1+b1) (tf32-rounded)
// tf32-rounded weight copies
__device__ float g_wq [C_*C_];
__device__ float g_wk [C_*C_];
__device__ float g_wv [C_*C_];
__device__ float g_wo [C_*C_];
__device__ float g_w1 [C_*FF];
__device__ float g_w2 [FF*C_];

// ---------------- small helpers ----------------
__device__ __forceinline__ uint32_t cvt_tf32(float x) {
    uint32_t r;
    asm("cvt.rna.tf32.f32 %0, %1;" : "=r"(r) : "f"(x));
    return r;
}
__device__ __forceinline__ float round_tf32(float x) {
    return __uint_as_float(cvt_tf32(x));
}
__device__ __forceinline__ uint32_t smem_u32(const void* p) {
    uint32_t a;
    asm("{ .reg .u64 t; cvta.to.shared.u64 t, %1; cvt.u32.u64 %0, t; }"
        : "=r"(a) : "l"(p));
    return a;
}
__device__ __forceinline__ void cp_async16(uint32_t s, const void* g) {
    asm volatile("cp.async.cg.shared.global [%0], [%1], 16;" :: "r"(s), "l"(g));
}
__device__ __forceinline__ void cp_commit() {
    asm volatile("cp.async.commit_group;");
}
__device__ __forceinline__ void cp_wait0() {
    asm volatile("cp.async.wait_group 0;");
}
__device__ __forceinline__ void cp_wait1() {
    asm volatile("cp.async.wait_group 1;");
}
__device__ __forceinline__ void mma_tf32(float* acc, const uint32_t* a,
                                         uint32_t b0, uint32_t b1) {
    asm volatile(
        "mma.sync.aligned.m16n8k8.row.col.f32.tf32.tf32.f32 "
        "{%0,%1,%2,%3},{%4,%5,%6,%7},{%8,%9},{%0,%1,%2,%3};"
        : "+f"(acc[0]), "+f"(acc[1]), "+f"(acc[2]), "+f"(acc[3])
        : "r"(a[0]), "r"(a[1]), "r"(a[2]), "r"(a[3]), "r"(b0), "r"(b1));
}

// ---------------- weight tf32 pre-rounding ----------------
__global__ void cvt_w_kernel(const float* __restrict__ s,
                             float* __restrict__ d, int n4) {
    int i = blockIdx.x * blockDim.x + threadIdx.x;
    if (i >= n4) return;
    float4 v = ((const float4*)s)[i];
    v.x = round_tf32(v.x); v.y = round_tf32(v.y);
    v.z = round_tf32(v.z); v.w = round_tf32(v.w);
    ((float4*)d)[i] = v;
}

// ---------------- block reduction (256 threads) ----------------
__device__ __forceinline__ float block_sum256(float v) {
    __shared__ float red[8];
    #pragma unroll
    for (int o = 16; o; o >>= 1) v += __shfl_xor_sync(0xffffffffu, v, o);
    __syncthreads();
    if ((threadIdx.x & 31) == 0) red[threadIdx.x >> 5] = v;
    __syncthreads();
    float s = 0.f;
    #pragma unroll
    for (int i = 0; i < 8; i++) s += red[i];
    return s;
}

// ---------------- LayerNorm: one block per row (output tf32-rounded) -----
__global__ void ln_kernel(const float* __restrict__ x,
                          const float* __restrict__ g,
                          const float* __restrict__ b,
                          float* __restrict__ out) {
    int row = blockIdx.x;
    const float4* xr = (const float4*)(x + (size_t)row * C_);
    float4 xa = xr[threadIdx.x];

    float s = xa.x + xa.y + xa.z + xa.w;
    float mu = block_sum256(s) * (1.0f / C_);

    float dx = xa.x - mu, dy = xa.y - mu, dz = xa.z - mu, dw = xa.w - mu;
    float sq = dx*dx + dy*dy + dz*dz + dw*dw;
    float var = block_sum256(sq) * (1.0f / C_);
    float rstd = rsqrtf(var + 1e-5f);

    float4 gg = ((const float4*)g)[threadIdx.x];
    float4 bb = ((const float4*)b)[threadIdx.x];
    float4 o;
    o.x = round_tf32(dx * rstd * gg.x + bb.x);
    o.y = round_tf32(dy * rstd * gg.y + bb.y);
    o.z = round_tf32(dz * rstd * gg.z + bb.z);
    o.w = round_tf32(dw * rstd * gg.w + bb.w);
    ((float4*)(out + (size_t)row * C_))[threadIdx.x] = o;
}

// ================= tf32 tensor-core GEMM (3-stage pipelined) =============
#define AS_STRIDE (128*36)
#define BS_STRIDE (32*136)
#define STAGE_STRIDE (AS_STRIDE + BS_STRIDE)
#define GEMM_SMEM_BYTES (3 * STAGE_STRIDE * 4)

template <int EPI, bool ROUND>
__device__ __forceinline__ void gemm_tc_body(
        const float* __restrict__ A, const float* __restrict__ Bm,
        const float* __restrict__ bias, const float* __restrict__ res,
        float* __restrict__ Cm, int M, int N, int K,
        int bx, int by) {
    extern __shared__ float smem[];

    const int tx   = threadIdx.x;
    const int warp = tx >> 5;
    const int lane = tx & 31;
    const int g    = lane >> 2;
    const int t    = lane & 3;
    const int wr   = (warp >> 2) * 64;
    const int wc   = (warp & 3) * 32;
    const int brow = by * 128;
    const int bcol = bx * 128;

    float acc[4][4][4];
    #pragma unroll
    for (int mt = 0; mt < 4; mt++)
        #pragma unroll
        for (int nt = 0; nt < 4; nt++)
            #pragma unroll
            for (int i = 0; i < 4; i++) acc[mt][nt][i] = 0.f;

    const int ar0 = tx >> 3;
    const int ak4 = tx & 7;
    const int bk0 = tx >> 5;
    const int bn4 = tx & 31;

    const float* Ag = A + (size_t)brow * K + ak4 * 4;
    const float* Bg = Bm + (size_t)bk0 * N + bcol + bn4 * 4;
    const int ntiles = K >> 5;

    auto issue = [&](int kt, int s) {
        if (kt < ntiles) {
            float* As = smem + s * STAGE_STRIDE;
            float* Bs = As + AS_STRIDE;
            const float* ag = Ag + kt * 32;
            const float* bg = Bg + (size_t)kt * 32 * N;
            #pragma unroll
            for (int i = 0; i < 4; i++) {
                int r = ar0 + 32 * i;
                cp_async16(smem_u32(As + r * 36 + ak4 * 4), ag + (size_t)r * K);
            }
            #pragma unroll
            for (int i = 0; i < 4; i++) {
                int kr = bk0 + 8 * i;
                cp_async16(smem_u32(Bs + kr * 136 + bn4 * 4), bg + (size_t)(8 * i) * N);
            }
        }
        cp_commit();
    };

    issue(0, 0);
    issue(1, 1);

    int s_c = 0;
    int s_w = 2;
    for (int kt = 0; kt < ntiles; kt++) {
        cp_wait1();
        __syncthreads();
        issue(kt + 2, s_w);

        const float* As = smem + s_c * STAGE_STRIDE;
        const float* Bs = As + AS_STRIDE;

        #pragma unroll
        for (int ks = 0; ks < 4; ks++) {
            uint32_t af[4][4], bf[4][2];
            #pragma unroll
            for (int mt = 0; mt < 4; mt++) {
                int m0 = wr + mt * 16 + g;
                af[mt][0] = __float_as_uint(As[(m0    ) * 36 + ks * 8 + t    ]);
                af[mt][1] = __float_as_uint(As[(m0 + 8) * 36 + ks * 8 + t    ]);
                af[mt][2] = __float_as_uint(As[(m0    ) * 36 + ks * 8 + t + 4]);
                af[mt][3] = __float_as_uint(As[(m0 + 8) * 36 + ks * 8 + t + 4]);
            }
            #pragma unroll
            for (int nt = 0; nt < 4; nt++) {
                int n0 = wc + nt * 8 + g;
                bf[nt][0] = __float_as_uint(Bs[(ks * 8 + t    ) * 136 + n0]);
                bf[nt][1] = __float_as_uint(Bs[(ks * 8 + t + 4) * 136 + n0]);
            }
            #pragma unroll
            for (int mt = 0; mt < 4; mt++)
                #pragma unroll
                for (int nt = 0; nt < 4; nt++)
                    mma_tf32(acc[mt][nt], af[mt], bf[nt][0], bf[nt][1]);
        }
        s_c = (s_c == 2) ? 0 : s_c + 1;
        s_w = (s_w == 2) ? 0 : s_w + 1;
    }

    #pragma unroll
    for (int mt = 0; mt < 4; mt++) {
        #pragma unroll
        for (int half = 0; half < 2; half++) {
            int row = brow + wr + mt * 16 + g + half * 8;
            #pragma unroll
            for (int nt = 0; nt < 4; nt++) {
                int col = bcol + wc + nt * 8 + 2 * t;
                float2 o;
                o.x = acc[mt][nt][half * 2 + 0];
                o.y = acc[mt][nt][half * 2 + 1];
                if (EPI >= 1) { o.x += bias[col]; o.y += bias[col + 1]; }
                if (EPI == 1) { o.x = fmaxf(o.x, 0.f); o.y = fmaxf(o.y, 0.f); }
                if (EPI == 2) {
                    float2 rr = *(const float2*)(res + (size_t)row * N + col);
                    o.x += rr.x; o.y += rr.y;
                }
                if (ROUND) { o.x = round_tf32(o.x); o.y = round_tf32(o.y); }
                *(float2*)(Cm + (size_t)row * N + col) = o;
            }
        }
    }
}

template <int EPI, bool ROUND>
__global__ void __launch_bounds__(256, 2)
gemm_tc(const float* __restrict__ A,
        const float* __restrict__ Bm,
        const float* __restrict__ bias,
        const float* __restrict__ res,
        float* __restrict__ Cm,
        int M, int N, int K) {
    gemm_tc_body<EPI, ROUND>(A, Bm, bias, res, Cm, M, N, K, blockIdx.x, blockIdx.y);
}

// fused QKV: blockIdx.z selects weight/output; outputs tf32-rounded
__global__ void __launch_bounds__(256, 2)
gemm_tc_qkv(const float* __restrict__ A,
            const float* __restrict__ W0,
            const float* __restrict__ W1,
            const float* __restrict__ W2,
            float* __restrict__ C0,
            float* __restrict__ C1,
            float* __restrict__ C2,
            int M, int N, int K) {
    const float* W = (blockIdx.z == 0) ? W0 : (blockIdx.z == 1) ? W1 : W2;
    float*       Cc = (blockIdx.z == 0) ? C0 : (blockIdx.z == 1) ? C1 : C2;
    gemm_tc_body<0, true>(A, W, nullptr, nullptr, Cc, M, N, K, blockIdx.x, blockIdx.y);
}

// ============ tensor-core causal flash attention (tf32) ==================
// grid: (T/64 q-tiles reversed, B*H). block: 128 threads = 4 warps.
// Br = Bc = 64, HD = 64. Warp tile: 16 rows x 64 keys (softmax warp-local).
// smem (dynamic):
//   Qs [64][68]  (A operand, 4g+t conflict-free)
//   Ks [2][64][68] ([key][d]; doubles as P [row][key] after S)
//   Vs [2][64][72] (natural [key][d]; stride 72 -> 8t+g conflict-free B reads)
#define ATT_KS_OFF   (64*68)
#define ATT_VS_OFF   (3*64*68)
#define ATT_SMEM_BYTES ((3*64*68 + 2*64*72) * 4)

__global__ void __launch_bounds__(128, 2)
attn_tc_kernel(const float* __restrict__ q,
               const float* __restrict__ k,
               const float* __restrict__ v,
               float* __restrict__ o) {
    extern __shared__ float sm[];
    float* Qs  = sm;
    float* KsB = sm + ATT_KS_OFF;   // stage s: KsB + s*4352
    float* VsB = sm + ATT_VS_OFF;   // stage s: VsB + s*4608

    const int tx   = threadIdx.x;
    const int w    = tx >> 5;
    const int lane = tx & 31;
    const int g    = lane >> 2;
    const int t    = lane & 3;
    const int bh   = blockIdx.y;
    const int b    = bh >> 4;
    const int h    = bh & 15;
    const int qt   = gridDim.x - 1 - blockIdx.x;   // big tiles first
    const int t0   = qt * 64;
    const size_t base = (size_t)b * T_ * C_ + (size_t)h * HD_;

    // prologue: Q + K0 + V0 (one cp.async group)
    #pragma unroll
    for (int i = 0; i < 8; i++) {
        int f = tx + 128 * i;
        int row = f >> 4, d4 = (f & 15) * 4;
        cp_async16(smem_u32(Qs  + row * 68 + d4), q + base + (size_t)(t0 + row) * C_ + d4);
        cp_async16(smem_u32(KsB + row * 68 + d4), k + base + (size_t)row * C_ + d4);
        cp_async16(smem_u32(VsB + row * 72 + d4), v + base + (size_t)row * C_ + d4);
    }
    cp_commit();

    float acc_o[8][4];
    #pragma unroll
    for (int nt = 0; nt < 8; nt++)
        #pragma unroll
        for (int i = 0; i < 4; i++) acc_o[nt][i] = 0.f;
    float mrow[2] = {-1e30f, -1e30f};
    float lrow[2] = {0.f, 0.f};

    int buf = 0;
    const int r0base = (w * 16 + g) * 68;

    for (int j = 0; j <= qt; j++) {
        cp_wait0();
        __syncthreads();   // data j ready; all warps done with prior P/V reads

        if (j < qt) {      // prefetch tile j+1 into the other stage
            float* Kn = KsB + (buf ^ 1) * 4352;
            float* Vn = VsB + (buf ^ 1) * 4608;
            const float* kg = k + base + (size_t)(j + 1) * 64 * C_;
            const float* vg = v + base + (size_t)(j + 1) * 64 * C_;
            #pragma unroll
            for (int i = 0; i < 8; i++) {
                int f = tx + 128 * i;
                int row = f >> 4, d4 = (f & 15) * 4;
                cp_async16(smem_u32(Kn + row * 68 + d4), kg + (size_t)row * C_ + d4);
                cp_async16(smem_u32(Vn + row * 72 + d4), vg + (size_t)row * C_ + d4);
            }
            cp_commit();
        }

        const float* Ks = KsB + buf * 4352;
        const float* Vs = VsB + buf * 4608;

        // ---- S = Q @ K^T ----
        float acc_s[8][4];
        #pragma unroll
        for (int nt = 0; nt < 8; nt++)
            #pragma unroll
            for (int i = 0; i < 4; i++) acc_s[nt][i] = 0.f;

        #pragma unroll
        for (int ks = 0; ks < 8; ks++) {
            uint32_t af[4];
            af[0] = __float_as_uint(Qs[r0base           + ks * 8 + t    ]);
            af[1] = __float_as_uint(Qs[r0base + 8 * 68  + ks * 8 + t    ]);
            af[2] = __float_as_uint(Qs[r0base           + ks * 8 + t + 4]);
            af[3] = __float_as_uint(Qs[r0base + 8 * 68  + ks * 8 + t + 4]);
            #pragma unroll
            for (int nt = 0; nt < 8; nt++) {
                int n0 = (nt * 8 + g) * 68 + ks * 8;
                mma_tf32(acc_s[nt], af,
                         __float_as_uint(Ks[n0 + t]),
                         __float_as_uint(Ks[n0 + t + 4]));
            }
        }

        // ---- online softmax (warp-local, quad reduce) ----
        const int kt0 = j * 64;
        #pragma unroll
        for (int half = 0; half < 2; half++) {
            const int rowg = t0 + w * 16 + g + half * 8;
            float rmax = -1e30f;
            #pragma unroll
            for (int nt = 0; nt < 8; nt++) {
                float s0 = acc_s[nt][2 * half    ] * 0.125f;
                float s1 = acc_s[nt][2 * half + 1] * 0.125f;
                if (j == qt) {
                    if (kt0 + nt * 8 + 2 * t     > rowg) s0 = -1e30f;
                    if (kt0 + nt * 8 + 2 * t + 1 > rowg) s1 = -1e30f;
                }
                acc_s[nt][2 * half]     = s0;
                acc_s[nt][2 * half + 1] = s1;
                rmax = fmaxf(rmax, fmaxf(s0, s1));
            }
            rmax = fmaxf(rmax, __shfl_xor_sync(0xffffffffu, rmax, 1));
            rmax = fmaxf(rmax, __shfl_xor_sync(0xffffffffu, rmax, 2));
            float mnew  = fmaxf(mrow[half], rmax);
            float alpha = __expf(mrow[half] - mnew);
            mrow[half] = mnew;
            float rsum = 0.f;
            #pragma unroll
            for (int nt = 0; nt < 8; nt++) {
                float p0 = __expf(acc_s[nt][2 * half]     - mnew);
                float p1 = __expf(acc_s[nt][2 * half + 1] - mnew);
                acc_s[nt][2 * half]     = p0;
                acc_s[nt][2 * half + 1] = p1;
                rsum += p0 + p1;
                acc_o[nt][2 * half]     *= alpha;
                acc_o[nt][2 * half + 1] *= alpha;
            }
            rsum += __shfl_xor_sync(0xffffffffu, rsum, 1);
            rsum += __shfl_xor_sync(0xffffffffu, rsum, 2);
            lrow[half] = lrow[half] * alpha + rsum;
        }

        __syncthreads();   // all warps done reading Ks as K

        // ---- write P (tf32-rounded) into the K buffer: [row][key] ----
        float* Ps = KsB + buf * 4352;
        #pragma unroll
        for (int nt = 0; nt < 8; nt++) {
            int col = nt * 8 + 2 * t;
            float2 p01, p23;
            p01.x = round_tf32(acc_s[nt][0]);
            p01.y = round_tf32(acc_s[nt][1]);
            p23.x = round_tf32(acc_s[nt][2]);
            p23.y = round_tf32(acc_s[nt][3]);
            *(float2*)&Ps[r0base + col]          = p01;
            *(float2*)&Ps[r0base + 8 * 68 + col] = p23;
        }
        __syncthreads();

        // ---- O += P @ V ----
        #pragma unroll
        for (int ks = 0; ks < 8; ks++) {
            uint32_t af[4];
            af[0] = __float_as_uint(Ps[r0base          + ks * 8 + t    ]);
            af[1] = __float_as_uint(Ps[r0base + 8 * 68 + ks * 8 + t    ]);
            af[2] = __float_as_uint(Ps[r0base          + ks * 8 + t + 4]);
            af[3] = __float_as_uint(Ps[r0base + 8 * 68 + ks * 8 + t + 4]);
            #pragma unroll
            for (int nt = 0; nt < 8; nt++) {
                int n0 = nt * 8 + g;
                mma_tf32(acc_o[nt], af,
                         __float_as_uint(Vs[(ks * 8 + t    ) * 72 + n0]),
                         __float_as_uint(Vs[(ks * 8 + t + 4) * 72 + n0]));
            }
        }
        buf ^= 1;
    }

    // ---- epilogue: normalize, round, store ----
    #pragma unroll
    for (int half = 0; half < 2; half++) {
        float inv = 1.f / lrow[half];
        int row = t0 + w * 16 + g + half * 8;
        #pragma unroll
        for (int nt = 0; nt < 8; nt++) {
            float2 ov;
            ov.x = round_tf32(acc_o[nt][2 * half]     * inv);
            ov.y = round_tf32(acc_o[nt][2 * half + 1] * inv);
            *(float2*)(o + base + (size_t)row * C_ + nt * 8 + 2 * t) = ov;
        }
    }
}

// ---------------- launch ----------------
extern "C" void kernel_launch(void* const* d_in, const int* in_sizes, int n_in,
                              void* d_out, int out_size) {
    const float* x    = (const float*)d_in[0];
    const float* Wq   = (const float*)d_in[1];
    const float* Wk   = (const float*)d_in[2];
    const float* Wv   = (const float*)d_in[3];
    const float* Wo   = (const float*)d_in[4];
    const float* bo   = (const float*)d_in[5];
    const float* ln1g = (const float*)d_in[6];
    const float* ln1b = (const float*)d_in[7];
    const float* ln2g = (const float*)d_in[8];
    const float* ln2b = (const float*)d_in[9];
    const float* W1   = (const float*)d_in[10];
    const float* b1   = (const float*)d_in[11];
    const float* W2   = (const float*)d_in[12];
    const float* b2   = (const float*)d_in[13];
    float* out = (float*)d_out;

    float *h, *q, *k, *v, *att, *x2, *h2, *ff1;
    float *wq, *wk, *wv, *wo, *w1, *w2;
    cudaGetSymbolAddress((void**)&h,   g_h);
    cudaGetSymbolAddress((void**)&q,   g_q);
    cudaGetSymbolAddress((void**)&k,   g_k);
    cudaGetSymbolAddress((void**)&v,   g_v);
    cudaGetSymbolAddress((void**)&att, g_att);
    cudaGetSymbolAddress((void**)&x2,  g_x2);
    cudaGetSymbolAddress((void**)&h2,  g_h2);
    cudaGetSymbolAddress((void**)&ff1, g_ff1);
    cudaGetSymbolAddress((void**)&wq,  g_wq);
    cudaGetSymbolAddress((void**)&wk,  g_wk);
    cudaGetSymbolAddress((void**)&wv,  g_wv);
    cudaGetSymbolAddress((void**)&wo,  g_wo);
    cudaGetSymbolAddress((void**)&w1,  g_w1);
    cudaGetSymbolAddress((void**)&w2,  g_w2);

    cudaFuncSetAttribute(gemm_tc<0,false>, cudaFuncAttributeMaxDynamicSharedMemorySize, GEMM_SMEM_BYTES);
    cudaFuncSetAttribute(gemm_tc<1,true>,  cudaFuncAttributeMaxDynamicSharedMemorySize, GEMM_SMEM_BYTES);
    cudaFuncSetAttribute(gemm_tc<2,false>, cudaFuncAttributeMaxDynamicSharedMemorySize, GEMM_SMEM_BYTES);
    cudaFuncSetAttribute(gemm_tc_qkv,      cudaFuncAttributeMaxDynamicSharedMemorySize, GEMM_SMEM_BYTES);
    cudaFuncSetAttribute(attn_tc_kernel,   cudaFuncAttributeMaxDynamicSharedMemorySize, ATT_SMEM_BYTES);

    // 0. pre-round weights to tf32 (stored as fp32 bits)
    const int CC4 = C_ * C_ / 4, CF4 = C_ * FF / 4;
    cvt_w_kernel<<<CC4 / 256, 256>>>(Wq, wq, CC4);
    cvt_w_kernel<<<CC4 / 256, 256>>>(Wk, wk, CC4);
    cvt_w_kernel<<<CC4 / 256, 256>>>(Wv, wv, CC4);
    cvt_w_kernel<<<CC4 / 256, 256>>>(Wo, wo, CC4);
    cvt_w_kernel<<<CF4 / 256, 256>>>(W1, w1, CF4);
    cvt_w_kernel<<<CF4 / 256, 256>>>(W2, w2, CF4);

    // 1. h = LN1(x)  (rounded)
    ln_kernel<<<NR, 256>>>(x, ln1g, ln1b, h);

    // 2. q,k,v = h @ {Wq,Wk,Wv}  (rounded outputs)
    gemm_tc_qkv<<<dim3(C_ / 128, NR / 128, 3), 256, GEMM_SMEM_BYTES>>>(
        h, wq, wk, wv, q, k, v, NR, C_, C_);

    // 3. causal attention (tensor-core, rounded output)
    attn_tc_kernel<<<dim3(T_ / 64, B_ * H_), 128, ATT_SMEM_BYTES>>>(q, k, v, att);

    // 4. x2 = x + att @ Wo + bo
    gemm_tc<2,false><<<dim3(C_ / 128, NR / 128), 256, GEMM_SMEM_BYTES>>>(att, wo, bo, x, x2, NR, C_, C_);

    // 5. h2 = LN2(x2)  (rounded)
    ln_kernel<<<NR, 256>>>(x2, ln2g, ln2b, h2);

    // 6. ff1 = relu(h2 @ W1 + b1)  (rounded)
    gemm_tc<1,true><<<dim3(FF / 128, NR / 128), 256, GEMM_SMEM_BYTES>>>(h2, w1, b1, nullptr, ff1, NR, FF, C_);

    // 7. out = x2 + ff1 @ W2 + b2
    gemm_tc<2,false><<<dim3(C_ / 128, NR / 128), 256, GEMM_SMEM_BYTES>>>(ff1, w2, b2, x2, out, NR, C_, FF);
}

// round 6
// speedup vs baseline: 4.1565x; 1.0284x over previous
#include <cuda_runtime.h>
#include <cstdint>

// Problem constants
#define B_  2
#define T_  2048
#define C_  1024
#define H_  16
#define HD_ 64
#define NR  (B_*T_)          // 4096 rows
#define FF  (4*C_)           // 4096

// ---------------- scratch (no allocations allowed) ----------------
__device__ float g_h  [NR*C_];   // ln1 out (tf32-rounded)
__device__ float g_q  [NR*C_];   // tf32-rounded
__device__ float g_k  [NR*C_];   // tf32-rounded
__device__ float g_v  [NR*C_];   // tf32-rounded
__device__ float g_att[NR*C_];   // attention out (tf32-rounded)
__device__ float g_x2 [NR*C_];   // post-attention residual
__device__ float g_h2 [NR*C_];   // ln2 out (tf32-rounded)
__device__ float g_ff1[NR*FF];   // relu(h2@W1+b1) (tf32-rounded)
// tf32-rounded weight copies
__device__ float g_wq [C_*C_];
__device__ float g_wk [C_*C_];
__device__ float g_wv [C_*C_];
__device__ float g_wo [C_*C_];
__device__ float g_w1 [C_*FF];
__device__ float g_w2 [FF*C_];

// ---------------- small helpers ----------------
__device__ __forceinline__ uint32_t cvt_tf32(float x) {
    uint32_t r;
    asm("cvt.rna.tf32.f32 %0, %1;" : "=r"(r) : "f"(x));
    return r;
}
__device__ __forceinline__ float round_tf32(float x) {
    return __uint_as_float(cvt_tf32(x));
}
__device__ __forceinline__ uint32_t smem_u32(const void* p) {
    uint32_t a;
    asm("{ .reg .u64 t; cvta.to.shared.u64 t, %1; cvt.u32.u64 %0, t; }"
        : "=r"(a) : "l"(p));
    return a;
}
__device__ __forceinline__ void cp_async16(uint32_t s, const void* g) {
    asm volatile("cp.async.cg.shared.global [%0], [%1], 16;" :: "r"(s), "l"(g));
}
__device__ __forceinline__ void cp_commit() {
    asm volatile("cp.async.commit_group;");
}
__device__ __forceinline__ void cp_wait0() {
    asm volatile("cp.async.wait_group 0;");
}
__device__ __forceinline__ void cp_wait1() {
    asm volatile("cp.async.wait_group 1;");
}
__device__ __forceinline__ void mma_tf32(float* acc, const uint32_t* a,
                                         uint32_t b0, uint32_t b1) {
    asm volatile(
        "mma.sync.aligned.m16n8k8.row.col.f32.tf32.tf32.f32 "
        "{%0,%1,%2,%3},{%4,%5,%6,%7},{%8,%9},{%0,%1,%2,%3};"
        : "+f"(acc[0]), "+f"(acc[1]), "+f"(acc[2]), "+f"(acc[3])
        : "r"(a[0]), "r"(a[1]), "r"(a[2]), "r"(a[3]), "r"(b0), "r"(b1));
}

// ---------------- fused weight tf32 pre-rounding (single launch) ---------
// Regions (in float4 units): [0,2^18)x4 = Wq,Wk,Wv,Wo; [2^20,2*2^20)=W1;
// [2*2^20,3*2^20)=W2. Total 3*2^20 float4.
__global__ void cvt_all_kernel(const float* __restrict__ Wq,
                               const float* __restrict__ Wk,
                               const float* __restrict__ Wv,
                               const float* __restrict__ Wo,
                               const float* __restrict__ W1,
                               const float* __restrict__ W2,
                               float* __restrict__ wq, float* __restrict__ wk,
                               float* __restrict__ wv, float* __restrict__ wo,
                               float* __restrict__ w1, float* __restrict__ w2) {
    int i = blockIdx.x * blockDim.x + threadIdx.x;
    const float4* s;
    float4* d;
    int off;
    if (i < (1 << 20)) {
        int r = i >> 18;
        off = i & 0x3FFFF;
        s = (const float4*)(r == 0 ? Wq : r == 1 ? Wk : r == 2 ? Wv : Wo);
        d = (float4*)(r == 0 ? wq : r == 1 ? wk : r == 2 ? wv : wo);
    } else if (i < (2 << 20)) {
        off = i - (1 << 20);
        s = (const float4*)W1; d = (float4*)w1;
    } else {
        off = i - (2 << 20);
        s = (const float4*)W2; d = (float4*)w2;
    }
    float4 v = s[off];
    v.x = round_tf32(v.x); v.y = round_tf32(v.y);
    v.z = round_tf32(v.z); v.w = round_tf32(v.w);
    d[off] = v;
}

// ---------------- block reduction (256 threads) ----------------
__device__ __forceinline__ float block_sum256(float v) {
    __shared__ float red[8];
    #pragma unroll
    for (int o = 16; o; o >>= 1) v += __shfl_xor_sync(0xffffffffu, v, o);
    __syncthreads();
    if ((threadIdx.x & 31) == 0) red[threadIdx.x >> 5] = v;
    __syncthreads();
    float s = 0.f;
    #pragma unroll
    for (int i = 0; i < 8; i++) s += red[i];
    return s;
}

// ---------------- LayerNorm: one block per row (output tf32-rounded) -----
__global__ void ln_kernel(const float* __restrict__ x,
                          const float* __restrict__ g,
                          const float* __restrict__ b,
                          float* __restrict__ out) {
    int row = blockIdx.x;
    const float4* xr = (const float4*)(x + (size_t)row * C_);
    float4 xa = xr[threadIdx.x];

    float s = xa.x + xa.y + xa.z + xa.w;
    float mu = block_sum256(s) * (1.0f / C_);

    float dx = xa.x - mu, dy = xa.y - mu, dz = xa.z - mu, dw = xa.w - mu;
    float sq = dx*dx + dy*dy + dz*dz + dw*dw;
    float var = block_sum256(sq) * (1.0f / C_);
    float rstd = rsqrtf(var + 1e-5f);

    float4 gg = ((const float4*)g)[threadIdx.x];
    float4 bb = ((const float4*)b)[threadIdx.x];
    float4 o;
    o.x = round_tf32(dx * rstd * gg.x + bb.x);
    o.y = round_tf32(dy * rstd * gg.y + bb.y);
    o.z = round_tf32(dz * rstd * gg.z + bb.z);
    o.w = round_tf32(dw * rstd * gg.w + bb.w);
    ((float4*)(out + (size_t)row * C_))[threadIdx.x] = o;
}

// ================= tf32 tensor-core GEMM (3-stage pipelined) =============
// C[MxN] = A[MxK] @ B[KxN] (+bias)(+relu)(+residual)
// BM=128, BN=128, BK=32; 128 threads = 4 warps (2x2); warp tile 64x64
// (mt=4 x nt=8 m16n8k8 tiles) -> each A fragment feeds 8 MMAs.
// 3 smem stages, one __syncthreads per k-tile.
#define AS_STRIDE (128*36)   // pad 4: LDS bank = 4g+t (bijective per warp)
#define BS_STRIDE (32*136)   // pad 8: LDS bank = 8t+g (bijective per warp)
#define STAGE_STRIDE (AS_STRIDE + BS_STRIDE)
#define GEMM_SMEM_BYTES (3 * STAGE_STRIDE * 4)

template <int EPI, bool ROUND>
__device__ __forceinline__ void gemm_tc_body(
        const float* __restrict__ A, const float* __restrict__ Bm,
        const float* __restrict__ bias, const float* __restrict__ res,
        float* __restrict__ Cm, int M, int N, int K,
        int bx, int by) {
    extern __shared__ float smem[];

    const int tx   = threadIdx.x;          // 0..127
    const int warp = tx >> 5;              // 0..3
    const int lane = tx & 31;
    const int g    = lane >> 2;
    const int t    = lane & 3;
    const int wr   = (warp >> 1) * 64;     // warp row (0/64)
    const int wc   = (warp & 1) * 64;      // warp col (0/64)
    const int brow = by * 128;
    const int bcol = bx * 128;

    float acc[4][8][4];
    #pragma unroll
    for (int mt = 0; mt < 4; mt++)
        #pragma unroll
        for (int nt = 0; nt < 8; nt++)
            #pragma unroll
            for (int i = 0; i < 4; i++) acc[mt][nt][i] = 0.f;

    // cp.async mapping: 128 threads, 8 f4 each for A and B
    const int ar0 = tx >> 3;           // A rows: ar0 + 16*i  (0..15)
    const int ak4 = tx & 7;
    const int bk0 = tx >> 5;           // B k-rows: bk0 + 4*i (0..3)
    const int bn4 = tx & 31;

    const float* Ag = A + (size_t)brow * K + ak4 * 4;
    const float* Bg = Bm + (size_t)bk0 * N + bcol + bn4 * 4;
    const int ntiles = K >> 5;

    auto issue = [&](int kt, int s) {
        if (kt < ntiles) {
            float* As = smem + s * STAGE_STRIDE;
            float* Bs = As + AS_STRIDE;
            const float* ag = Ag + kt * 32;
            const float* bg = Bg + (size_t)kt * 32 * N;
            #pragma unroll
            for (int i = 0; i < 8; i++) {
                int r = ar0 + 16 * i;
                cp_async16(smem_u32(As + r * 36 + ak4 * 4), ag + (size_t)r * K);
            }
            #pragma unroll
            for (int i = 0; i < 8; i++) {
                int kr = bk0 + 4 * i;
                cp_async16(smem_u32(Bs + kr * 136 + bn4 * 4), bg + (size_t)(4 * i) * N);
            }
        }
        cp_commit();   // always commit so wait_group counts stay aligned
    };

    issue(0, 0);
    issue(1, 1);

    int s_c = 0;
    int s_w = 2;
    for (int kt = 0; kt < ntiles; kt++) {
        cp_wait1();
        __syncthreads();
        issue(kt + 2, s_w);

        const float* As = smem + s_c * STAGE_STRIDE;
        const float* Bs = As + AS_STRIDE;

        #pragma unroll
        for (int ks = 0; ks < 4; ks++) {
            uint32_t af[4][4], bf[8][2];
            #pragma unroll
            for (int mt = 0; mt < 4; mt++) {
                int m0 = wr + mt * 16 + g;
                af[mt][0] = __float_as_uint(As[(m0    ) * 36 + ks * 8 + t    ]);
                af[mt][1] = __float_as_uint(As[(m0 + 8) * 36 + ks * 8 + t    ]);
                af[mt][2] = __float_as_uint(As[(m0    ) * 36 + ks * 8 + t + 4]);
                af[mt][3] = __float_as_uint(As[(m0 + 8) * 36 + ks * 8 + t + 4]);
            }
            #pragma unroll
            for (int nt = 0; nt < 8; nt++) {
                int n0 = wc + nt * 8 + g;
                bf[nt][0] = __float_as_uint(Bs[(ks * 8 + t    ) * 136 + n0]);
                bf[nt][1] = __float_as_uint(Bs[(ks * 8 + t + 4) * 136 + n0]);
            }
            #pragma unroll
            for (int mt = 0; mt < 4; mt++)
                #pragma unroll
                for (int nt = 0; nt < 8; nt++)
                    mma_tf32(acc[mt][nt], af[mt], bf[nt][0], bf[nt][1]);
        }
        s_c = (s_c == 2) ? 0 : s_c + 1;
        s_w = (s_w == 2) ? 0 : s_w + 1;
    }

    // epilogue: c0=(g,2t) c1=(g,2t+1) c2=(g+8,2t) c3=(g+8,2t+1)
    #pragma unroll
    for (int mt = 0; mt < 4; mt++) {
        #pragma unroll
        for (int half = 0; half < 2; half++) {
            int row = brow + wr + mt * 16 + g + half * 8;
            #pragma unroll
            for (int nt = 0; nt < 8; nt++) {
                int col = bcol + wc + nt * 8 + 2 * t;
                float2 o;
                o.x = acc[mt][nt][half * 2 + 0];
                o.y = acc[mt][nt][half * 2 + 1];
                if (EPI >= 1) { o.x += bias[col]; o.y += bias[col + 1]; }
                if (EPI == 1) { o.x = fmaxf(o.x, 0.f); o.y = fmaxf(o.y, 0.f); }
                if (EPI == 2) {
                    float2 rr = *(const float2*)(res + (size_t)row * N + col);
                    o.x += rr.x; o.y += rr.y;
                }
                if (ROUND) { o.x = round_tf32(o.x); o.y = round_tf32(o.y); }
                *(float2*)(Cm + (size_t)row * N + col) = o;
            }
        }
    }
}

template <int EPI, bool ROUND>
__global__ void __launch_bounds__(128, 2)
gemm_tc(const float* __restrict__ A,
        const float* __restrict__ Bm,
        const float* __restrict__ bias,
        const float* __restrict__ res,
        float* __restrict__ Cm,
        int M, int N, int K) {
    gemm_tc_body<EPI, ROUND>(A, Bm, bias, res, Cm, M, N, K, blockIdx.x, blockIdx.y);
}

// fused QKV: blockIdx.z selects weight/output; outputs tf32-rounded
__global__ void __launch_bounds__(128, 2)
gemm_tc_qkv(const float* __restrict__ A,
            const float* __restrict__ W0,
            const float* __restrict__ W1,
            const float* __restrict__ W2,
            float* __restrict__ C0,
            float* __restrict__ C1,
            float* __restrict__ C2,
            int M, int N, int K) {
    const float* W = (blockIdx.z == 0) ? W0 : (blockIdx.z == 1) ? W1 : W2;
    float*       Cc = (blockIdx.z == 0) ? C0 : (blockIdx.z == 1) ? C1 : C2;
    gemm_tc_body<0, true>(A, W, nullptr, nullptr, Cc, M, N, K, blockIdx.x, blockIdx.y);
}

// ============ tensor-core causal flash attention (tf32) ==================
// grid: (T/64 q-tiles reversed, B*H). block: 128 threads = 4 warps.
// Br = Bc = 64, HD = 64. Warp tile: 16 rows x 64 keys (softmax warp-local).
#define ATT_KS_OFF   (64*68)
#define ATT_VS_OFF   (3*64*68)
#define ATT_SMEM_BYTES ((3*64*68 + 2*64*72) * 4)

__global__ void __launch_bounds__(128, 2)
attn_tc_kernel(const float* __restrict__ q,
               const float* __restrict__ k,
               const float* __restrict__ v,
               float* __restrict__ o) {
    extern __shared__ float sm[];
    float* Qs  = sm;
    float* KsB = sm + ATT_KS_OFF;   // stage s: KsB + s*4352
    float* VsB = sm + ATT_VS_OFF;   // stage s: VsB + s*4608

    const int tx   = threadIdx.x;
    const int w    = tx >> 5;
    const int lane = tx & 31;
    const int g    = lane >> 2;
    const int t    = lane & 3;
    const int bh   = blockIdx.y;
    const int b    = bh >> 4;
    const int h    = bh & 15;
    const int qt   = gridDim.x - 1 - blockIdx.x;   // big tiles first
    const int t0   = qt * 64;
    const size_t base = (size_t)b * T_ * C_ + (size_t)h * HD_;

    // prologue: Q + K0 + V0 (one cp.async group)
    #pragma unroll
    for (int i = 0; i < 8; i++) {
        int f = tx + 128 * i;
        int row = f >> 4, d4 = (f & 15) * 4;
        cp_async16(smem_u32(Qs  + row * 68 + d4), q + base + (size_t)(t0 + row) * C_ + d4);
        cp_async16(smem_u32(KsB + row * 68 + d4), k + base + (size_t)row * C_ + d4);
        cp_async16(smem_u32(VsB + row * 72 + d4), v + base + (size_t)row * C_ + d4);
    }
    cp_commit();

    float acc_o[8][4];
    #pragma unroll
    for (int nt = 0; nt < 8; nt++)
        #pragma unroll
        for (int i = 0; i < 4; i++) acc_o[nt][i] = 0.f;
    float mrow[2] = {-1e30f, -1e30f};
    float lrow[2] = {0.f, 0.f};

    int buf = 0;
    const int r0base = (w * 16 + g) * 68;

    for (int j = 0; j <= qt; j++) {
        cp_wait0();
        __syncthreads();   // data j ready; all warps done with prior P/V reads

        if (j < qt) {      // prefetch tile j+1 into the other stage
            float* Kn = KsB + (buf ^ 1) * 4352;
            float* Vn = VsB + (buf ^ 1) * 4608;
            const float* kg = k + base + (size_t)(j + 1) * 64 * C_;
            const float* vg = v + base + (size_t)(j + 1) * 64 * C_;
            #pragma unroll
            for (int i = 0; i < 8; i++) {
                int f = tx + 128 * i;
                int row = f >> 4, d4 = (f & 15) * 4;
                cp_async16(smem_u32(Kn + row * 68 + d4), kg + (size_t)row * C_ + d4);
                cp_async16(smem_u32(Vn + row * 72 + d4), vg + (size_t)row * C_ + d4);
            }
            cp_commit();
        }

        const float* Ks = KsB + buf * 4352;
        const float* Vs = VsB + buf * 4608;

        // ---- S = Q @ K^T ----
        float acc_s[8][4];
        #pragma unroll
        for (int nt = 0; nt < 8; nt++)
            #pragma unroll
            for (int i = 0; i < 4; i++) acc_s[nt][i] = 0.f;

        #pragma unroll
        for (int ks = 0; ks < 8; ks++) {
            uint32_t af[4];
            af[0] = __float_as_uint(Qs[r0base           + ks * 8 + t    ]);
            af[1] = __float_as_uint(Qs[r0base + 8 * 68  + ks * 8 + t    ]);
            af[2] = __float_as_uint(Qs[r0base           + ks * 8 + t + 4]);
            af[3] = __float_as_uint(Qs[r0base + 8 * 68  + ks * 8 + t + 4]);
            #pragma unroll
            for (int nt = 0; nt < 8; nt++) {
                int n0 = (nt * 8 + g) * 68 + ks * 8;
                mma_tf32(acc_s[nt], af,
                         __float_as_uint(Ks[n0 + t]),
                         __float_as_uint(Ks[n0 + t + 4]));
            }
        }

        // ---- online softmax (warp-local, quad reduce) ----
        const int kt0 = j * 64;
        #pragma unroll
        for (int half = 0; half < 2; half++) {
            const int rowg = t0 + w * 16 + g + half * 8;
            float rmax = -1e30f;
            #pragma unroll
            for (int nt = 0; nt < 8; nt++) {
                float s0 = acc_s[nt][2 * half    ] * 0.125f;
                float s1 = acc_s[nt][2 * half + 1] * 0.125f;
                if (j == qt) {
                    if (kt0 + nt * 8 + 2 * t     > rowg) s0 = -1e30f;
                    if (kt0 + nt * 8 + 2 * t + 1 > rowg) s1 = -1e30f;
                }
                acc_s[nt][2 * half]     = s0;
                acc_s[nt][2 * half + 1] = s1;
                rmax = fmaxf(rmax, fmaxf(s0, s1));
            }
            rmax = fmaxf(rmax, __shfl_xor_sync(0xffffffffu, rmax, 1));
            rmax = fmaxf(rmax, __shfl_xor_sync(0xffffffffu, rmax, 2));
            float mnew  = fmaxf(mrow[half], rmax);
            float alpha = __expf(mrow[half] - mnew);
            mrow[half] = mnew;
            float rsum = 0.f;
            #pragma unroll
            for (int nt = 0; nt < 8; nt++) {
                float p0 = __expf(acc_s[nt][2 * half]     - mnew);
                float p1 = __expf(acc_s[nt][2 * half + 1] - mnew);
                acc_s[nt][2 * half]     = p0;
                acc_s[nt][2 * half + 1] = p1;
                rsum += p0 + p1;
                acc_o[nt][2 * half]     *= alpha;
                acc_o[nt][2 * half + 1] *= alpha;
            }
            rsum += __shfl_xor_sync(0xffffffffu, rsum, 1);
            rsum += __shfl_xor_sync(0xffffffffu, rsum, 2);
            lrow[half] = lrow[half] * alpha + rsum;
        }

        __syncthreads();   // all warps done reading Ks as K

        // ---- write P (tf32-rounded) into the K buffer: [row][key] ----
        float* Ps = KsB + buf * 4352;
        #pragma unroll
        for (int nt = 0; nt < 8; nt++) {
            int col = nt * 8 + 2 * t;
            float2 p01, p23;
            p01.x = round_tf32(acc_s[nt][0]);
            p01.y = round_tf32(acc_s[nt][1]);
            p23.x = round_tf32(acc_s[nt][2]);
            p23.y = round_tf32(acc_s[nt][3]);
            *(float2*)&Ps[r0base + col]          = p01;
            *(float2*)&Ps[r0base + 8 * 68 + col] = p23;
        }
        __syncthreads();

        // ---- O += P @ V ----
        #pragma unroll
        for (int ks = 0; ks < 8; ks++) {
            uint32_t af[4];
            af[0] = __float_as_uint(Ps[r0base          + ks * 8 + t    ]);
            af[1] = __float_as_uint(Ps[r0base + 8 * 68 + ks * 8 + t    ]);
            af[2] = __float_as_uint(Ps[r0base          + ks * 8 + t + 4]);
            af[3] = __float_as_uint(Ps[r0base + 8 * 68 + ks * 8 + t + 4]);
            #pragma unroll
            for (int nt = 0; nt < 8; nt++) {
                int n0 = nt * 8 + g;
                mma_tf32(acc_o[nt], af,
                         __float_as_uint(Vs[(ks * 8 + t    ) * 72 + n0]),
                         __float_as_uint(Vs[(ks * 8 + t + 4) * 72 + n0]));
            }
        }
        buf ^= 1;
    }

    // ---- epilogue: normalize, round, store ----
    #pragma unroll
    for (int half = 0; half < 2; half++) {
        float inv = 1.f / lrow[half];
        int row = t0 + w * 16 + g + half * 8;
        #pragma unroll
        for (int nt = 0; nt < 8; nt++) {
            float2 ov;
            ov.x = round_tf32(acc_o[nt][2 * half]     * inv);
            ov.y = round_tf32(acc_o[nt][2 * half + 1] * inv);
            *(float2*)(o + base + (size_t)row * C_ + nt * 8 + 2 * t) = ov;
        }
    }
}

// ---------------- launch ----------------
extern "C" void kernel_launch(void* const* d_in, const int* in_sizes, int n_in,
                              void* d_out, int out_size) {
    const float* x    = (const float*)d_in[0];
    const float* Wq   = (const float*)d_in[1];
    const float* Wk   = (const float*)d_in[2];
    const float* Wv   = (const float*)d_in[3];
    const float* Wo   = (const float*)d_in[4];
    const float* bo   = (const float*)d_in[5];
    const float* ln1g = (const float*)d_in[6];
    const float* ln1b = (const float*)d_in[7];
    const float* ln2g = (const float*)d_in[8];
    const float* ln2b = (const float*)d_in[9];
    const float* W1   = (const float*)d_in[10];
    const float* b1   = (const float*)d_in[11];
    const float* W2   = (const float*)d_in[12];
    const float* b2   = (const float*)d_in[13];
    float* out = (float*)d_out;

    float *h, *q, *k, *v, *att, *x2, *h2, *ff1;
    float *wq, *wk, *wv, *wo, *w1, *w2;
    cudaGetSymbolAddress((void**)&h,   g_h);
    cudaGetSymbolAddress((void**)&q,   g_q);
    cudaGetSymbolAddress((void**)&k,   g_k);
    cudaGetSymbolAddress((void**)&v,   g_v);
    cudaGetSymbolAddress((void**)&att, g_att);
    cudaGetSymbolAddress((void**)&x2,  g_x2);
    cudaGetSymbolAddress((void**)&h2,  g_h2);
    cudaGetSymbolAddress((void**)&ff1, g_ff1);
    cudaGetSymbolAddress((void**)&wq,  g_wq);
    cudaGetSymbolAddress((void**)&wk,  g_wk);
    cudaGetSymbolAddress((void**)&wv,  g_wv);
    cudaGetSymbolAddress((void**)&wo,  g_wo);
    cudaGetSymbolAddress((void**)&w1,  g_w1);
    cudaGetSymbolAddress((void**)&w2,  g_w2);

    cudaFuncSetAttribute(gemm_tc<0,false>, cudaFuncAttributeMaxDynamicSharedMemorySize, GEMM_SMEM_BYTES);
    cudaFuncSetAttribute(gemm_tc<1,true>,  cudaFuncAttributeMaxDynamicSharedMemorySize, GEMM_SMEM_BYTES);
    cudaFuncSetAttribute(gemm_tc<2,false>, cudaFuncAttributeMaxDynamicSharedMemorySize, GEMM_SMEM_BYTES);
    cudaFuncSetAttribute(gemm_tc_qkv,      cudaFuncAttributeMaxDynamicSharedMemorySize, GEMM_SMEM_BYTES);
    cudaFuncSetAttribute(attn_tc_kernel,   cudaFuncAttributeMaxDynamicSharedMemorySize, ATT_SMEM_BYTES);

    // 0. pre-round all weights to tf32 (one launch)
    cvt_all_kernel<<<(3 << 20) / 256, 256>>>(Wq, Wk, Wv, Wo, W1, W2,
                                             wq, wk, wv, wo, w1, w2);

    // 1. h = LN1(x)  (rounded)
    ln_kernel<<<NR, 256>>>(x, ln1g, ln1b, h);

    // 2. q,k,v = h @ {Wq,Wk,Wv}  (rounded outputs)
    gemm_tc_qkv<<<dim3(C_ / 128, NR / 128, 3), 128, GEMM_SMEM_BYTES>>>(
        h, wq, wk, wv, q, k, v, NR, C_, C_);

    // 3. causal attention (tensor-core, rounded output)
    attn_tc_kernel<<<dim3(T_ / 64, B_ * H_), 128, ATT_SMEM_BYTES>>>(q, k, v, att);

    // 4. x2 = x + att @ Wo + bo
    gemm_tc<2,false><<<dim3(C_ / 128, NR / 128), 128, GEMM_SMEM_BYTES>>>(att, wo, bo, x, x2, NR, C_, C_);

    // 5. h2 = LN2(x2)  (rounded)
    ln_kernel<<<NR, 256>>>(x2, ln2g, ln2b, h2);

    // 6. ff1 = relu(h2 @ W1 + b1)  (rounded)
    gemm_tc<1,true><<<dim3(FF / 128, NR / 128), 128, GEMM_SMEM_BYTES>>>(h2, w1, b1, nullptr, ff1, NR, FF, C_);

    // 7. out = x2 + ff1 @ W2 + b2
    gemm_tc<2,false><<<dim3(C_ / 128, NR / 128), 128, GEMM_SMEM_BYTES>>>(ff1, w2, b2, x2, out, NR, C_, FF);
}

// round 8
// speedup vs baseline: 8.1215x; 1.9539x over previous
#include <cuda_runtime.h>
#include <cuda_fp16.h>
#include <cstdint>

// Problem constants
#define B_  2
#define T_  2048
#define C_  1024
#define H_  16
#define HD_ 64
#define NR  (B_*T_)          // 4096 rows
#define FF  (4*C_)           // 4096

// ---------------- scratch (no allocations allowed) ----------------
__device__ __half g_h  [NR*C_];   // ln1 out (fp16)
__device__ __half g_q  [NR*C_];
__device__ __half g_k  [NR*C_];
__device__ __half g_v  [NR*C_];
__device__ __half g_att[NR*C_];
__device__ float  g_x2 [NR*C_];   // post-attention residual (fp32)
__device__ __half g_h2 [NR*C_];
__device__ __half g_ff1[NR*FF];
// fp16, TRANSPOSED weight copies ([N][K] layout)
__device__ __half g_wq [C_*C_];
__device__ __half g_wk [C_*C_];
__device__ __half g_wv [C_*C_];
__device__ __half g_wo [C_*C_];
__device__ __half g_w1 [C_*FF];   // [4096][1024]
__device__ __half g_w2 [FF*C_];   // [1024][4096]

// ---------------- small helpers ----------------
__device__ __forceinline__ uint32_t smem_u32(const void* p) {
    uint32_t a;
    asm("{ .reg .u64 t; cvta.to.shared.u64 t, %1; cvt.u32.u64 %0, t; }"
        : "=r"(a) : "l"(p));
    return a;
}
__device__ __forceinline__ void cp_async16(uint32_t s, const void* g) {
    asm volatile("cp.async.cg.shared.global [%0], [%1], 16;" :: "r"(s), "l"(g));
}
__device__ __forceinline__ void cp_commit() {
    asm volatile("cp.async.commit_group;");
}
__device__ __forceinline__ void cp_wait0() {
    asm volatile("cp.async.wait_group 0;");
}
__device__ __forceinline__ void cp_wait1() {
    asm volatile("cp.async.wait_group 1;");
}
__device__ __forceinline__ void ldsm_x4(uint32_t* r, uint32_t addr) {
    asm volatile("ldmatrix.sync.aligned.m8n8.x4.shared.b16 {%0,%1,%2,%3}, [%4];"
        : "=r"(r[0]), "=r"(r[1]), "=r"(r[2]), "=r"(r[3]) : "r"(addr));
}
__device__ __forceinline__ void ldsm_x4_t(uint32_t* r, uint32_t addr) {
    asm volatile("ldmatrix.sync.aligned.m8n8.x4.trans.shared.b16 {%0,%1,%2,%3}, [%4];"
        : "=r"(r[0]), "=r"(r[1]), "=r"(r[2]), "=r"(r[3]) : "r"(addr));
}
__device__ __forceinline__ void mma_f16(float* acc, const uint32_t* a,
                                        uint32_t b0, uint32_t b1) {
    asm volatile(
        "mma.sync.aligned.m16n8k16.row.col.f32.f16.f16.f32 "
        "{%0,%1,%2,%3},{%4,%5,%6,%7},{%8,%9},{%0,%1,%2,%3};"
        : "+f"(acc[0]), "+f"(acc[1]), "+f"(acc[2]), "+f"(acc[3])
        : "r"(a[0]), "r"(a[1]), "r"(a[2]), "r"(a[3]), "r"(b0), "r"(b1));
}

// -------- fused fp16-convert + transpose of all weights: W[K,N]->Wt[N,K] ---
__global__ void cvt_t_kernel(const float* __restrict__ Wq, const float* __restrict__ Wk,
                             const float* __restrict__ Wv, const float* __restrict__ Wo,
                             const float* __restrict__ W1, const float* __restrict__ W2,
                             __half* __restrict__ wq, __half* __restrict__ wk,
                             __half* __restrict__ wv, __half* __restrict__ wo,
                             __half* __restrict__ w1, __half* __restrict__ w2) {
    __shared__ float tile[32][33];
    int bid = blockIdx.x;
    const float* S; __half* D; int K, N, t;
    if (bid < 4096) {
        int r = bid >> 10; t = bid & 1023; K = 1024; N = 1024;
        S = r == 0 ? Wq : r == 1 ? Wk : r == 2 ? Wv : Wo;
        D = r == 0 ? wq : r == 1 ? wk : r == 2 ? wv : wo;
    } else if (bid < 8192) {
        t = bid - 4096; K = 1024; N = 4096; S = W1; D = w1;
    } else {
        t = bid - 8192; K = 4096; N = 1024; S = W2; D = w2;
    }
    int tnc = N >> 5;
    int tk = (t / tnc) << 5;
    int tn = (t % tnc) << 5;
    int c  = threadIdx.x & 31, r8 = threadIdx.x >> 5;
    #pragma unroll
    for (int i = 0; i < 4; i++) {
        int kk = tk + r8 + i * 8;
        tile[r8 + i * 8][c] = S[(size_t)kk * N + tn + c];
    }
    __syncthreads();
    #pragma unroll
    for (int i = 0; i < 4; i++) {
        int nn = tn + r8 + i * 8;
        D[(size_t)nn * K + tk + c] = __float2half_rn(tile[c][r8 + i * 8]);
    }
}

// ---------------- block reduction (256 threads) ----------------
__device__ __forceinline__ float block_sum256(float v) {
    __shared__ float red[8];
    #pragma unroll
    for (int o = 16; o; o >>= 1) v += __shfl_xor_sync(0xffffffffu, v, o);
    __syncthreads();
    if ((threadIdx.x & 31) == 0) red[threadIdx.x >> 5] = v;
    __syncthreads();
    float s = 0.f;
    #pragma unroll
    for (int i = 0; i < 8; i++) s += red[i];
    return s;
}

// ---------------- LayerNorm: fp32 in, fp16 out ----------------
__global__ void ln_kernel(const float* __restrict__ x,
                          const float* __restrict__ g,
                          const float* __restrict__ b,
                          __half* __restrict__ out) {
    int row = blockIdx.x;
    const float4* xr = (const float4*)(x + (size_t)row * C_);
    float4 xa = xr[threadIdx.x];

    float s = xa.x + xa.y + xa.z + xa.w;
    float mu = block_sum256(s) * (1.0f / C_);

    float dx = xa.x - mu, dy = xa.y - mu, dz = xa.z - mu, dw = xa.w - mu;
    float sq = dx*dx + dy*dy + dz*dz + dw*dw;
    float var = block_sum256(sq) * (1.0f / C_);
    float rstd = rsqrtf(var + 1e-5f);

    float4 gg = ((const float4*)g)[threadIdx.x];
    float4 bb = ((const float4*)b)[threadIdx.x];
    __half2* od = (__half2*)(out + (size_t)row * C_);
    od[2 * threadIdx.x    ] = __floats2half2_rn(dx * rstd * gg.x + bb.x,
                                                dy * rstd * gg.y + bb.y);
    od[2 * threadIdx.x + 1] = __floats2half2_rn(dz * rstd * gg.z + bb.z,
                                                dw * rstd * gg.w + bb.w);
}

// ============ fp16 tensor-core GEMM: C = A[M,K] @ Bt[N,K]^T ===============
// BM=128, BN=128, BK=32; 128 threads = 4 warps (2x2); warp tile 64x64
// (mt=4 x nt=8 m16n8k16). ldmatrix.x4 fragment loads; 3 cp.async stages.
// smem per stage: A 128x40 half (10240B) + B 128x40 half -> 20480B; x3.
// EPI: 0 none (half out), 1 bias+relu (half out), 2 bias+residual (float out)
#define GEMM_SMEM_BYTES (3 * 20480)

template <int EPI>
__device__ __forceinline__ void gemm_h_body(
        const __half* __restrict__ A, const __half* __restrict__ Bt,
        const float* __restrict__ bias, const float* __restrict__ res,
        void* __restrict__ Cm, int M, int N, int K, int bx, int by) {
    extern __shared__ char smraw[];
    const uint32_t sb = smem_u32(smraw);

    const int tx   = threadIdx.x;
    const int warp = tx >> 5;
    const int lane = tx & 31;
    const int g    = lane >> 2;
    const int t    = lane & 3;
    const int wr   = (warp >> 1) * 64;
    const int wc   = (warp & 1) * 64;
    const int brow = by * 128;
    const int bcol = bx * 128;

    // ldmatrix per-lane offsets (bytes), stride 40 halves = 80B
    const int a_row = lane & 15;
    const int a_k8  = (lane >> 4) * 8;
    const int b_n   = (lane & 7) + (lane >> 4) * 8;
    const int b_k8  = ((lane >> 3) & 1) * 8;
    const uint32_t aoff = ((wr + a_row) * 40 + a_k8) * 2;
    const uint32_t boff = ((wc + b_n)   * 40 + b_k8) * 2;

    float acc[4][8][4];
    #pragma unroll
    for (int mt = 0; mt < 4; mt++)
        #pragma unroll
        for (int nt = 0; nt < 8; nt++)
            #pragma unroll
            for (int i = 0; i < 4; i++) acc[mt][nt][i] = 0.f;

    const int ntiles = K >> 5;
    auto load_tile = [&](int kt, int s) {
        if (kt < ntiles) {
            uint32_t ab = sb + s * 20480;
            uint32_t bb2 = ab + 10240;
            const __half* ag = A  + (size_t)brow * K + kt * 32;
            const __half* bg = Bt + (size_t)bcol * K + kt * 32;
            #pragma unroll
            for (int i = 0; i < 4; i++) {
                int f = tx + 128 * i, row = f >> 2, ch = f & 3;
                uint32_t d = row * 80 + ch * 16;
                cp_async16(ab + d,  ag + (size_t)row * K + ch * 8);
                cp_async16(bb2 + d, bg + (size_t)row * K + ch * 8);
            }
        }
        cp_commit();   // always commit to keep wait counts aligned
    };

    load_tile(0, 0);
    load_tile(1, 1);

    int s_c = 0, s_w = 2;
    for (int kt = 0; kt < ntiles; kt++) {
        cp_wait1();
        __syncthreads();
        load_tile(kt + 2, s_w);

        const uint32_t ab = sb + s_c * 20480;
        const uint32_t bb2 = ab + 10240;

        #pragma unroll
        for (int ks = 0; ks < 2; ks++) {
            uint32_t a[4][4], bq[4][4];
            #pragma unroll
            for (int mt = 0; mt < 4; mt++)
                ldsm_x4(a[mt], ab + aoff + mt * 1280 + ks * 32);
            #pragma unroll
            for (int nt2 = 0; nt2 < 4; nt2++)
                ldsm_x4(bq[nt2], bb2 + boff + nt2 * 1280 + ks * 32);
            #pragma unroll
            for (int mt = 0; mt < 4; mt++)
                #pragma unroll
                for (int nt = 0; nt < 8; nt++)
                    mma_f16(acc[mt][nt], a[mt],
                            bq[nt >> 1][(nt & 1) * 2],
                            bq[nt >> 1][(nt & 1) * 2 + 1]);
        }
        s_c = (s_c == 2) ? 0 : s_c + 1;
        s_w = (s_w == 2) ? 0 : s_w + 1;
    }

    // epilogue: c0=(g,2t) c1=(g,2t+1) c2=(g+8,2t) c3=(g+8,2t+1)
    #pragma unroll
    for (int mt = 0; mt < 4; mt++) {
        #pragma unroll
        for (int hh = 0; hh < 2; hh++) {
            int row = brow + wr + mt * 16 + g + hh * 8;
            #pragma unroll
            for (int nt = 0; nt < 8; nt++) {
                int col = bcol + wc + nt * 8 + 2 * t;
                float ox = acc[mt][nt][hh * 2 + 0];
                float oy = acc[mt][nt][hh * 2 + 1];
                if (EPI >= 1) { ox += bias[col]; oy += bias[col + 1]; }
                if (EPI == 1) { ox = fmaxf(ox, 0.f); oy = fmaxf(oy, 0.f); }
                if (EPI == 2) {
                    float2 rr = *(const float2*)(res + (size_t)row * N + col);
                    *(float2*)((float*)Cm + (size_t)row * N + col) =
                        make_float2(ox + rr.x, oy + rr.y);
                } else {
                    *(__half2*)((__half*)Cm + (size_t)row * N + col) =
                        __floats2half2_rn(ox, oy);
                }
            }
        }
    }
}

template <int EPI>
__global__ void __launch_bounds__(128, 2)
gemm_h(const __half* __restrict__ A, const __half* __restrict__ Bt,
       const float* __restrict__ bias, const float* __restrict__ res,
       void* __restrict__ Cm, int M, int N, int K) {
    gemm_h_body<EPI>(A, Bt, bias, res, Cm, M, N, K, blockIdx.x, blockIdx.y);
}

__global__ void __launch_bounds__(128, 2)
gemm_h_qkv(const __half* __restrict__ A,
           const __half* __restrict__ W0, const __half* __restrict__ W1,
           const __half* __restrict__ W2,
           __half* __restrict__ C0, __half* __restrict__ C1,
           __half* __restrict__ C2, int M, int N, int K) {
    const __half* W = (blockIdx.z == 0) ? W0 : (blockIdx.z == 1) ? W1 : W2;
    __half*      Cc = (blockIdx.z == 0) ? C0 : (blockIdx.z == 1) ? C1 : C2;
    gemm_h_body<0>(A, W, nullptr, nullptr, Cc, M, N, K, blockIdx.x, blockIdx.y);
}

// ============ fp16 tensor-core causal flash attention =====================
// grid: (T/64 q-tiles reversed, B*H). block: 128 threads = 4 warps.
// Br=Bc=64, HD=64. Warp tile 16 rows x 64 keys. Row stride 72 halves (144B).
// smem: Qs 9216B | K/P stages 2x9216 | V stages 2x9216 = 46080B.
#define KSOFF(s) (9216 + (s) * 9216)
#define VSOFF(s) (27648 + (s) * 9216)
#define ATT_SMEM_BYTES 46080

__global__ void __launch_bounds__(128, 3)
attn_h_kernel(const __half* __restrict__ q,
              const __half* __restrict__ k,
              const __half* __restrict__ v,
              __half* __restrict__ o) {
    extern __shared__ char smraw[];
    const uint32_t sb = smem_u32(smraw);

    const int tx   = threadIdx.x;
    const int w    = tx >> 5;
    const int lane = tx & 31;
    const int g    = lane >> 2;
    const int t    = lane & 3;
    const int bh   = blockIdx.y;
    const int b    = bh >> 4;
    const int h    = bh & 15;
    const int qt   = gridDim.x - 1 - blockIdx.x;   // big tiles first
    const int t0   = qt * 64;
    const size_t base = (size_t)b * T_ * C_ + (size_t)h * HD_;

    // ldmatrix per-lane offsets (stride 72 halves = 144B)
    const int a_row = lane & 15;
    const int a_k8  = (lane >> 4) * 8;
    const int b_n   = (lane & 7) + (lane >> 4) * 8;
    const int b_k8  = ((lane >> 3) & 1) * 8;
    const int v_k   = (lane & 7) + ((lane >> 3) & 1) * 8;
    const int v_c   = (lane >> 4) * 8;
    const uint32_t qoff = ((w * 16 + a_row) * 72 + a_k8) * 2;

    // prologue: Q + K0 + V0
    #pragma unroll
    for (int i = 0; i < 4; i++) {
        int f = tx + 128 * i, row = f >> 3, ch = f & 7;
        uint32_t d = row * 144 + ch * 16;
        cp_async16(sb + d,            q + base + (size_t)(t0 + row) * C_ + ch * 8);
        cp_async16(sb + KSOFF(0) + d, k + base + (size_t)row * C_ + ch * 8);
        cp_async16(sb + VSOFF(0) + d, v + base + (size_t)row * C_ + ch * 8);
    }
    cp_commit();

    float acc_o[8][4];
    #pragma unroll
    for (int nt = 0; nt < 8; nt++)
        #pragma unroll
        for (int i = 0; i < 4; i++) acc_o[nt][i] = 0.f;
    float mrow[2] = {-1e30f, -1e30f};
    float lrow[2] = {0.f, 0.f};

    int buf = 0;
    for (int j = 0; j <= qt; j++) {
        cp_wait0();
        __syncthreads();   // data j ready; prior-stage readers done

        if (j < qt) {
            const __half* kg = k + base + (size_t)(j + 1) * 64 * C_;
            const __half* vg = v + base + (size_t)(j + 1) * 64 * C_;
            #pragma unroll
            for (int i = 0; i < 4; i++) {
                int f = tx + 128 * i, row = f >> 3, ch = f & 7;
                uint32_t d = row * 144 + ch * 16;
                cp_async16(sb + KSOFF(buf ^ 1) + d, kg + (size_t)row * C_ + ch * 8);
                cp_async16(sb + VSOFF(buf ^ 1) + d, vg + (size_t)row * C_ + ch * 8);
            }
            cp_commit();
        }

        // ---- S = Q @ K^T ----
        float acc_s[8][4];
        #pragma unroll
        for (int nt = 0; nt < 8; nt++)
            #pragma unroll
            for (int i = 0; i < 4; i++) acc_s[nt][i] = 0.f;

        #pragma unroll
        for (int ks = 0; ks < 4; ks++) {
            uint32_t aq[4], bk[4][4];
            ldsm_x4(aq, sb + qoff + ks * 32);
            #pragma unroll
            for (int nt2 = 0; nt2 < 4; nt2++)
                ldsm_x4(bk[nt2], sb + KSOFF(buf) +
                        ((nt2 * 16 + b_n) * 72 + ks * 16 + b_k8) * 2);
            #pragma unroll
            for (int nt = 0; nt < 8; nt++)
                mma_f16(acc_s[nt], aq,
                        bk[nt >> 1][(nt & 1) * 2],
                        bk[nt >> 1][(nt & 1) * 2 + 1]);
        }

        // ---- online softmax (warp-local, quad reduce) ----
        const int kt0 = j * 64;
        #pragma unroll
        for (int hh = 0; hh < 2; hh++) {
            const int rowg = t0 + w * 16 + g + hh * 8;
            float rmax = -1e30f;
            #pragma unroll
            for (int nt = 0; nt < 8; nt++) {
                float s0 = acc_s[nt][2 * hh    ] * 0.125f;
                float s1 = acc_s[nt][2 * hh + 1] * 0.125f;
                if (j == qt) {
                    if (kt0 + nt * 8 + 2 * t     > rowg) s0 = -1e30f;
                    if (kt0 + nt * 8 + 2 * t + 1 > rowg) s1 = -1e30f;
                }
                acc_s[nt][2 * hh]     = s0;
                acc_s[nt][2 * hh + 1] = s1;
                rmax = fmaxf(rmax, fmaxf(s0, s1));
            }
            rmax = fmaxf(rmax, __shfl_xor_sync(0xffffffffu, rmax, 1));
            rmax = fmaxf(rmax, __shfl_xor_sync(0xffffffffu, rmax, 2));
            float mnew  = fmaxf(mrow[hh], rmax);
            float alpha = __expf(mrow[hh] - mnew);
            mrow[hh] = mnew;
            float rsum = 0.f;
            #pragma unroll
            for (int nt = 0; nt < 8; nt++) {
                float p0 = __expf(acc_s[nt][2 * hh]     - mnew);
                float p1 = __expf(acc_s[nt][2 * hh + 1] - mnew);
                acc_s[nt][2 * hh]     = p0;
                acc_s[nt][2 * hh + 1] = p1;
                rsum += p0 + p1;
                acc_o[nt][2 * hh]     *= alpha;
                acc_o[nt][2 * hh + 1] *= alpha;
            }
            rsum += __shfl_xor_sync(0xffffffffu, rsum, 1);
            rsum += __shfl_xor_sync(0xffffffffu, rsum, 2);
            lrow[hh] = lrow[hh] * alpha + rsum;
        }

        __syncthreads();   // all warps done reading Ks as K

        // ---- P (fp16) into the K buffer: [row][key], stride 72 ----
        char* Ps = smraw + KSOFF(buf);
        #pragma unroll
        for (int nt = 0; nt < 8; nt++) {
            int col = nt * 8 + 2 * t;
            *(__half2*)(Ps + ((w * 16 + g    ) * 72 + col) * 2) =
                __floats2half2_rn(acc_s[nt][0], acc_s[nt][1]);
            *(__half2*)(Ps + ((w * 16 + g + 8) * 72 + col) * 2) =
                __floats2half2_rn(acc_s[nt][2], acc_s[nt][3]);
        }
        __syncwarp();      // P rows are warp-private

        // ---- O += P @ V  (V via ldmatrix.trans from natural layout) ----
        #pragma unroll
        for (int ks = 0; ks < 4; ks++) {
            uint32_t ap[4], bv[4][4];
            ldsm_x4(ap, sb + KSOFF(buf) +
                    ((w * 16 + a_row) * 72 + ks * 16 + a_k8) * 2);
            #pragma unroll
            for (int nt2 = 0; nt2 < 4; nt2++)
                ldsm_x4_t(bv[nt2], sb + VSOFF(buf) +
                          ((ks * 16 + v_k) * 72 + nt2 * 16 + v_c) * 2);
            #pragma unroll
            for (int nt = 0; nt < 8; nt++)
                mma_f16(acc_o[nt], ap,
                        bv[nt >> 1][(nt & 1) * 2],
                        bv[nt >> 1][(nt & 1) * 2 + 1]);
        }
        buf ^= 1;
    }

    // ---- epilogue: normalize, store fp16 ----
    #pragma unroll
    for (int hh = 0; hh < 2; hh++) {
        float inv = 1.f / lrow[hh];
        int row = t0 + w * 16 + g + hh * 8;
        #pragma unroll
        for (int nt = 0; nt < 8; nt++) {
            *(__half2*)(o + base + (size_t)row * C_ + nt * 8 + 2 * t) =
                __floats2half2_rn(acc_o[nt][2 * hh] * inv,
                                  acc_o[nt][2 * hh + 1] * inv);
        }
    }
}

// ---------------- launch ----------------
extern "C" void kernel_launch(void* const* d_in, const int* in_sizes, int n_in,
                              void* d_out, int out_size) {
    const float* x    = (const float*)d_in[0];
    const float* Wq   = (const float*)d_in[1];
    const float* Wk   = (const float*)d_in[2];
    const float* Wv   = (const float*)d_in[3];
    const float* Wo   = (const float*)d_in[4];
    const float* bo   = (const float*)d_in[5];
    const float* ln1g = (const float*)d_in[6];
    const float* ln1b = (const float*)d_in[7];
    const float* ln2g = (const float*)d_in[8];
    const float* ln2b = (const float*)d_in[9];
    const float* W1   = (const float*)d_in[10];
    const float* b1   = (const float*)d_in[11];
    const float* W2   = (const float*)d_in[12];
    const float* b2   = (const float*)d_in[13];
    float* out = (float*)d_out;

    __half *h, *q, *k, *v, *att, *h2, *ff1;
    __half *wq, *wk, *wv, *wo, *w1, *w2;
    float *x2;
    cudaGetSymbolAddress((void**)&h,   g_h);
    cudaGetSymbolAddress((void**)&q,   g_q);
    cudaGetSymbolAddress((void**)&k,   g_k);
    cudaGetSymbolAddress((void**)&v,   g_v);
    cudaGetSymbolAddress((void**)&att, g_att);
    cudaGetSymbolAddress((void**)&x2,  g_x2);
    cudaGetSymbolAddress((void**)&h2,  g_h2);
    cudaGetSymbolAddress((void**)&ff1, g_ff1);
    cudaGetSymbolAddress((void**)&wq,  g_wq);
    cudaGetSymbolAddress((void**)&wk,  g_wk);
    cudaGetSymbolAddress((void**)&wv,  g_wv);
    cudaGetSymbolAddress((void**)&wo,  g_wo);
    cudaGetSymbolAddress((void**)&w1,  g_w1);
    cudaGetSymbolAddress((void**)&w2,  g_w2);

    cudaFuncSetAttribute(gemm_h<0>, cudaFuncAttributeMaxDynamicSharedMemorySize, GEMM_SMEM_BYTES);
    cudaFuncSetAttribute(gemm_h<1>, cudaFuncAttributeMaxDynamicSharedMemorySize, GEMM_SMEM_BYTES);
    cudaFuncSetAttribute(gemm_h<2>, cudaFuncAttributeMaxDynamicSharedMemorySize, GEMM_SMEM_BYTES);
    cudaFuncSetAttribute(gemm_h_qkv, cudaFuncAttributeMaxDynamicSharedMemorySize, GEMM_SMEM_BYTES);
    cudaFuncSetAttribute(attn_h_kernel, cudaFuncAttributeMaxDynamicSharedMemorySize, ATT_SMEM_BYTES);

    // 0. convert + transpose weights -> fp16 [N][K]
    cvt_t_kernel<<<12288, 256>>>(Wq, Wk, Wv, Wo, W1, W2, wq, wk, wv, wo, w1, w2);

    // 1. h = LN1(x)  (fp16 out)
    ln_kernel<<<NR, 256>>>(x, ln1g, ln1b, h);

    // 2. q,k,v = h @ {Wq,Wk,Wv}  (fp16)
    gemm_h_qkv<<<dim3(C_ / 128, NR / 128, 3), 128, GEMM_SMEM_BYTES>>>(
        h, wq, wk, wv, q, k, v, NR, C_, C_);

    // 3. causal attention (fp16)
    attn_h_kernel<<<dim3(T_ / 64, B_ * H_), 128, ATT_SMEM_BYTES>>>(q, k, v, att);

    // 4. x2 = x + att @ Wo + bo  (fp32 out)
    gemm_h<2><<<dim3(C_ / 128, NR / 128), 128, GEMM_SMEM_BYTES>>>(att, wo, bo, x, x2, NR, C_, C_);

    // 5. h2 = LN2(x2)  (fp16 out)
    ln_kernel<<<NR, 256>>>(x2, ln2g, ln2b, h2);

    // 6. ff1 = relu(h2 @ W1 + b1)  (fp16 out)
    gemm_h<1><<<dim3(FF / 128, NR / 128), 128, GEMM_SMEM_BYTES>>>(h2, w1, b1, nullptr, ff1, NR, FF, C_);

    // 7. out = x2 + ff1 @ W2 + b2  (fp32 out)
    gemm_h<2><<<dim3(C_ / 128, NR / 128), 128, GEMM_SMEM_BYTES>>>(ff1, w2, b2, x2, out, NR, C_, FF);
}

// round 9
// speedup vs baseline: 8.2329x; 1.0137x over previous
#include <cuda_runtime.h>
#include <cuda_fp16.h>
#include <cstdint>

// Problem constants
#define B_  2
#define T_  2048
#define C_  1024
#define H_  16
#define HD_ 64
#define NR  (B_*T_)          // 4096 rows
#define FF  (4*C_)           // 4096
#define QSCALE 0.18033688f   // 0.125 * log2(e), folded into q

// ---------------- scratch (no allocations allowed) ----------------
__device__ __half g_h  [NR*C_];   // ln1 out (fp16)
__device__ __half g_q  [NR*C_];   // pre-scaled by QSCALE
__device__ __half g_k  [NR*C_];
__device__ __half g_v  [NR*C_];
__device__ __half g_att[NR*C_];
__device__ float  g_x2 [NR*C_];   // post-attention residual (fp32)
__device__ __half g_h2 [NR*C_];
__device__ __half g_ff1[NR*FF];
// fp16, TRANSPOSED weight copies ([N][K] layout)
__device__ __half g_wq [C_*C_];
__device__ __half g_wk [C_*C_];
__device__ __half g_wv [C_*C_];
__device__ __half g_wo [C_*C_];
__device__ __half g_w1 [C_*FF];   // [4096][1024]
__device__ __half g_w2 [FF*C_];   // [1024][4096]

// ---------------- small helpers ----------------
__device__ __forceinline__ uint32_t smem_u32(const void* p) {
    uint32_t a;
    asm("{ .reg .u64 t; cvta.to.shared.u64 t, %1; cvt.u32.u64 %0, t; }"
        : "=r"(a) : "l"(p));
    return a;
}
__device__ __forceinline__ void cp_async16(uint32_t s, const void* g) {
    asm volatile("cp.async.cg.shared.global [%0], [%1], 16;" :: "r"(s), "l"(g));
}
__device__ __forceinline__ void cp_commit() {
    asm volatile("cp.async.commit_group;");
}
__device__ __forceinline__ void cp_wait0() {
    asm volatile("cp.async.wait_group 0;");
}
__device__ __forceinline__ void cp_wait2() {
    asm volatile("cp.async.wait_group 2;");
}
__device__ __forceinline__ float ex2f(float x) {   // raw MUFU.EX2
    float r;
    asm("ex2.approx.ftz.f32 %0, %1;" : "=f"(r) : "f"(x));
    return r;
}
__device__ __forceinline__ void ldsm_x4(uint32_t* r, uint32_t addr) {
    asm volatile("ldmatrix.sync.aligned.m8n8.x4.shared.b16 {%0,%1,%2,%3}, [%4];"
        : "=r"(r[0]), "=r"(r[1]), "=r"(r[2]), "=r"(r[3]) : "r"(addr));
}
__device__ __forceinline__ void ldsm_x4_t(uint32_t* r, uint32_t addr) {
    asm volatile("ldmatrix.sync.aligned.m8n8.x4.trans.shared.b16 {%0,%1,%2,%3}, [%4];"
        : "=r"(r[0]), "=r"(r[1]), "=r"(r[2]), "=r"(r[3]) : "r"(addr));
}
__device__ __forceinline__ void mma_f16(float* acc, const uint32_t* a,
                                        uint32_t b0, uint32_t b1) {
    asm volatile(
        "mma.sync.aligned.m16n8k16.row.col.f32.f16.f16.f32 "
        "{%0,%1,%2,%3},{%4,%5,%6,%7},{%8,%9},{%0,%1,%2,%3};"
        : "+f"(acc[0]), "+f"(acc[1]), "+f"(acc[2]), "+f"(acc[3])
        : "r"(a[0]), "r"(a[1]), "r"(a[2]), "r"(a[3]), "r"(b0), "r"(b1));
}

// -------- fused fp16-convert + transpose of all weights: W[K,N]->Wt[N,K] ---
__global__ void cvt_t_kernel(const float* __restrict__ Wq, const float* __restrict__ Wk,
                             const float* __restrict__ Wv, const float* __restrict__ Wo,
                             const float* __restrict__ W1, const float* __restrict__ W2,
                             __half* __restrict__ wq, __half* __restrict__ wk,
                             __half* __restrict__ wv, __half* __restrict__ wo,
                             __half* __restrict__ w1, __half* __restrict__ w2) {
    __shared__ float tile[32][33];
    int bid = blockIdx.x;
    const float* S; __half* D; int K, N, t;
    if (bid < 4096) {
        int r = bid >> 10; t = bid & 1023; K = 1024; N = 1024;
        S = r == 0 ? Wq : r == 1 ? Wk : r == 2 ? Wv : Wo;
        D = r == 0 ? wq : r == 1 ? wk : r == 2 ? wv : wo;
    } else if (bid < 8192) {
        t = bid - 4096; K = 1024; N = 4096; S = W1; D = w1;
    } else {
        t = bid - 8192; K = 4096; N = 1024; S = W2; D = w2;
    }
    int tnc = N >> 5;
    int tk = (t / tnc) << 5;
    int tn = (t % tnc) << 5;
    int c  = threadIdx.x & 31, r8 = threadIdx.x >> 5;
    #pragma unroll
    for (int i = 0; i < 4; i++) {
        int kk = tk + r8 + i * 8;
        tile[r8 + i * 8][c] = S[(size_t)kk * N + tn + c];
    }
    __syncthreads();
    #pragma unroll
    for (int i = 0; i < 4; i++) {
        int nn = tn + r8 + i * 8;
        D[(size_t)nn * K + tk + c] = __float2half_rn(tile[c][r8 + i * 8]);
    }
}

// ---------------- block reduction (256 threads) ----------------
__device__ __forceinline__ float block_sum256(float v) {
    __shared__ float red[8];
    #pragma unroll
    for (int o = 16; o; o >>= 1) v += __shfl_xor_sync(0xffffffffu, v, o);
    __syncthreads();
    if ((threadIdx.x & 31) == 0) red[threadIdx.x >> 5] = v;
    __syncthreads();
    float s = 0.f;
    #pragma unroll
    for (int i = 0; i < 8; i++) s += red[i];
    return s;
}

// ---------------- LayerNorm: fp32 in, fp16 out ----------------
__global__ void ln_kernel(const float* __restrict__ x,
                          const float* __restrict__ g,
                          const float* __restrict__ b,
                          __half* __restrict__ out) {
    int row = blockIdx.x;
    const float4* xr = (const float4*)(x + (size_t)row * C_);
    float4 xa = xr[threadIdx.x];

    float s = xa.x + xa.y + xa.z + xa.w;
    float mu = block_sum256(s) * (1.0f / C_);

    float dx = xa.x - mu, dy = xa.y - mu, dz = xa.z - mu, dw = xa.w - mu;
    float sq = dx*dx + dy*dy + dz*dz + dw*dw;
    float var = block_sum256(sq) * (1.0f / C_);
    float rstd = rsqrtf(var + 1e-5f);

    float4 gg = ((const float4*)g)[threadIdx.x];
    float4 bb = ((const float4*)b)[threadIdx.x];
    __half2* od = (__half2*)(out + (size_t)row * C_);
    od[2 * threadIdx.x    ] = __floats2half2_rn(dx * rstd * gg.x + bb.x,
                                                dy * rstd * gg.y + bb.y);
    od[2 * threadIdx.x + 1] = __floats2half2_rn(dz * rstd * gg.z + bb.z,
                                                dw * rstd * gg.w + bb.w);
}

// ============ fp16 tensor-core GEMM: C = A[M,K] @ Bt[N,K]^T ===============
// BM=128, BN=128, BK=32; 128 threads = 4 warps (2x2); warp tile 64x64.
// ldmatrix.x4 fragment loads; 4 cp.async stages, one barrier per k-tile.
// EPI: 0 none (half out, optional oscale), 1 bias+relu (half out),
//      2 bias+residual (float out)
#define GEMM_SMEM_BYTES (4 * 20480)

template <int EPI>
__device__ __forceinline__ void gemm_h_body(
        const __half* __restrict__ A, const __half* __restrict__ Bt,
        const float* __restrict__ bias, const float* __restrict__ res,
        void* __restrict__ Cm, int M, int N, int K, int bx, int by,
        float oscale) {
    extern __shared__ char smraw[];
    const uint32_t sb = smem_u32(smraw);

    const int tx   = threadIdx.x;
    const int warp = tx >> 5;
    const int lane = tx & 31;
    const int g    = lane >> 2;
    const int t    = lane & 3;
    const int wr   = (warp >> 1) * 64;
    const int wc   = (warp & 1) * 64;
    const int brow = by * 128;
    const int bcol = bx * 128;

    // ldmatrix per-lane offsets (bytes), stride 40 halves = 80B
    const int a_row = lane & 15;
    const int a_k8  = (lane >> 4) * 8;
    const int b_n   = (lane & 7) + (lane >> 4) * 8;
    const int b_k8  = ((lane >> 3) & 1) * 8;
    const uint32_t aoff = ((wr + a_row) * 40 + a_k8) * 2;
    const uint32_t boff = ((wc + b_n)   * 40 + b_k8) * 2;

    float acc[4][8][4];
    #pragma unroll
    for (int mt = 0; mt < 4; mt++)
        #pragma unroll
        for (int nt = 0; nt < 8; nt++)
            #pragma unroll
            for (int i = 0; i < 4; i++) acc[mt][nt][i] = 0.f;

    const int ntiles = K >> 5;
    auto load_tile = [&](int kt, int s) {
        if (kt < ntiles) {
            uint32_t ab = sb + s * 20480;
            uint32_t bb2 = ab + 10240;
            const __half* ag = A  + (size_t)brow * K + kt * 32;
            const __half* bg = Bt + (size_t)bcol * K + kt * 32;
            #pragma unroll
            for (int i = 0; i < 4; i++) {
                int f = tx + 128 * i, row = f >> 2, ch = f & 3;
                uint32_t d = row * 80 + ch * 16;
                cp_async16(ab + d,  ag + (size_t)row * K + ch * 8);
                cp_async16(bb2 + d, bg + (size_t)row * K + ch * 8);
            }
        }
        cp_commit();   // always commit to keep wait counts aligned
    };

    load_tile(0, 0);
    load_tile(1, 1);
    load_tile(2, 2);

    int s_c = 0, s_w = 3;
    for (int kt = 0; kt < ntiles; kt++) {
        cp_wait2();        // tile kt landed (<=2 younger groups in flight)
        __syncthreads();
        load_tile(kt + 3, s_w);

        const uint32_t ab = sb + s_c * 20480;
        const uint32_t bb2 = ab + 10240;

        #pragma unroll
        for (int ks = 0; ks < 2; ks++) {
            uint32_t a[4][4], bq[4][4];
            #pragma unroll
            for (int mt = 0; mt < 4; mt++)
                ldsm_x4(a[mt], ab + aoff + mt * 1280 + ks * 32);
            #pragma unroll
            for (int nt2 = 0; nt2 < 4; nt2++)
                ldsm_x4(bq[nt2], bb2 + boff + nt2 * 1280 + ks * 32);
            #pragma unroll
            for (int mt = 0; mt < 4; mt++)
                #pragma unroll
                for (int nt = 0; nt < 8; nt++)
                    mma_f16(acc[mt][nt], a[mt],
                            bq[nt >> 1][(nt & 1) * 2],
                            bq[nt >> 1][(nt & 1) * 2 + 1]);
        }
        s_c = (s_c + 1) & 3;
        s_w = (s_w + 1) & 3;
    }

    // epilogue: c0=(g,2t) c1=(g,2t+1) c2=(g+8,2t) c3=(g+8,2t+1)
    #pragma unroll
    for (int mt = 0; mt < 4; mt++) {
        #pragma unroll
        for (int hh = 0; hh < 2; hh++) {
            int row = brow + wr + mt * 16 + g + hh * 8;
            #pragma unroll
            for (int nt = 0; nt < 8; nt++) {
                int col = bcol + wc + nt * 8 + 2 * t;
                float ox = acc[mt][nt][hh * 2 + 0];
                float oy = acc[mt][nt][hh * 2 + 1];
                if (EPI >= 1) { ox += bias[col]; oy += bias[col + 1]; }
                if (EPI == 1) { ox = fmaxf(ox, 0.f); oy = fmaxf(oy, 0.f); }
                if (EPI == 2) {
                    float2 rr = *(const float2*)(res + (size_t)row * N + col);
                    *(float2*)((float*)Cm + (size_t)row * N + col) =
                        make_float2(ox + rr.x, oy + rr.y);
                } else {
                    if (EPI == 0) { ox *= oscale; oy *= oscale; }
                    *(__half2*)((__half*)Cm + (size_t)row * N + col) =
                        __floats2half2_rn(ox, oy);
                }
            }
        }
    }
}

template <int EPI>
__global__ void __launch_bounds__(128, 2)
gemm_h(const __half* __restrict__ A, const __half* __restrict__ Bt,
       const float* __restrict__ bias, const float* __restrict__ res,
       void* __restrict__ Cm, int M, int N, int K) {
    gemm_h_body<EPI>(A, Bt, bias, res, Cm, M, N, K, blockIdx.x, blockIdx.y, 1.0f);
}

__global__ void __launch_bounds__(128, 2)
gemm_h_qkv(const __half* __restrict__ A,
           const __half* __restrict__ W0, const __half* __restrict__ W1,
           const __half* __restrict__ W2,
           __half* __restrict__ C0, __half* __restrict__ C1,
           __half* __restrict__ C2, int M, int N, int K) {
    const __half* W = (blockIdx.z == 0) ? W0 : (blockIdx.z == 1) ? W1 : W2;
    __half*      Cc = (blockIdx.z == 0) ? C0 : (blockIdx.z == 1) ? C1 : C2;
    float sc = (blockIdx.z == 0) ? QSCALE : 1.0f;   // fold softmax scale into q
    gemm_h_body<0>(A, W, nullptr, nullptr, Cc, M, N, K, blockIdx.x, blockIdx.y, sc);
}

// ============ fp16 tensor-core causal flash attention (exp2 path) =========
// grid: (T/64 q-tiles reversed, B*H). block: 128 threads = 4 warps.
// Br=Bc=64, HD=64. Warp tile 16 rows x 64 keys. Row stride 72 halves (144B).
// q is pre-scaled by 0.125*log2e, so p = 2^(S - m) directly (MUFU.EX2).
#define KSOFF(s) (9216 + (s) * 9216)
#define VSOFF(s) (27648 + (s) * 9216)
#define ATT_SMEM_BYTES 46080

__global__ void __launch_bounds__(128, 3)
attn_h_kernel(const __half* __restrict__ q,
              const __half* __restrict__ k,
              const __half* __restrict__ v,
              __half* __restrict__ o) {
    extern __shared__ char smraw[];
    const uint32_t sb = smem_u32(smraw);

    const int tx   = threadIdx.x;
    const int w    = tx >> 5;
    const int lane = tx & 31;
    const int g    = lane >> 2;
    const int t    = lane & 3;
    const int bh   = blockIdx.y;
    const int b    = bh >> 4;
    const int h    = bh & 15;
    const int qt   = gridDim.x - 1 - blockIdx.x;   // big tiles first
    const int t0   = qt * 64;
    const size_t base = (size_t)b * T_ * C_ + (size_t)h * HD_;

    // ldmatrix per-lane offsets (stride 72 halves = 144B)
    const int a_row = lane & 15;
    const int a_k8  = (lane >> 4) * 8;
    const int b_n   = (lane & 7) + (lane >> 4) * 8;
    const int b_k8  = ((lane >> 3) & 1) * 8;
    const int v_k   = (lane & 7) + ((lane >> 3) & 1) * 8;
    const int v_c   = (lane >> 4) * 8;
    const uint32_t qoff = ((w * 16 + a_row) * 72 + a_k8) * 2;

    // prologue: Q + K0 + V0
    #pragma unroll
    for (int i = 0; i < 4; i++) {
        int f = tx + 128 * i, row = f >> 3, ch = f & 7;
        uint32_t d = row * 144 + ch * 16;
        cp_async16(sb + d,            q + base + (size_t)(t0 + row) * C_ + ch * 8);
        cp_async16(sb + KSOFF(0) + d, k + base + (size_t)row * C_ + ch * 8);
        cp_async16(sb + VSOFF(0) + d, v + base + (size_t)row * C_ + ch * 8);
    }
    cp_commit();

    float acc_o[8][4];
    #pragma unroll
    for (int nt = 0; nt < 8; nt++)
        #pragma unroll
        for (int i = 0; i < 4; i++) acc_o[nt][i] = 0.f;
    float mrow[2] = {-1e30f, -1e30f};
    float lrow[2] = {0.f, 0.f};

    int buf = 0;
    for (int j = 0; j <= qt; j++) {
        cp_wait0();
        __syncthreads();   // data j ready; prior-stage readers done

        if (j < qt) {
            const __half* kg = k + base + (size_t)(j + 1) * 64 * C_;
            const __half* vg = v + base + (size_t)(j + 1) * 64 * C_;
            #pragma unroll
            for (int i = 0; i < 4; i++) {
                int f = tx + 128 * i, row = f >> 3, ch = f & 7;
                uint32_t d = row * 144 + ch * 16;
                cp_async16(sb + KSOFF(buf ^ 1) + d, kg + (size_t)row * C_ + ch * 8);
                cp_async16(sb + VSOFF(buf ^ 1) + d, vg + (size_t)row * C_ + ch * 8);
            }
            cp_commit();
        }

        // ---- S = Q @ K^T  (already includes softmax scale via q) ----
        float acc_s[8][4];
        #pragma unroll
        for (int nt = 0; nt < 8; nt++)
            #pragma unroll
            for (int i = 0; i < 4; i++) acc_s[nt][i] = 0.f;

        #pragma unroll
        for (int ks = 0; ks < 4; ks++) {
            uint32_t aq[4], bk[4][4];
            ldsm_x4(aq, sb + qoff + ks * 32);
            #pragma unroll
            for (int nt2 = 0; nt2 < 4; nt2++)
                ldsm_x4(bk[nt2], sb + KSOFF(buf) +
                        ((nt2 * 16 + b_n) * 72 + ks * 16 + b_k8) * 2);
            #pragma unroll
            for (int nt = 0; nt < 8; nt++)
                mma_f16(acc_s[nt], aq,
                        bk[nt >> 1][(nt & 1) * 2],
                        bk[nt >> 1][(nt & 1) * 2 + 1]);
        }

        // ---- online softmax in log2 domain (warp-local, quad reduce) ----
        const int kt0 = j * 64;
        #pragma unroll
        for (int hh = 0; hh < 2; hh++) {
            const int rowg = t0 + w * 16 + g + hh * 8;
            float rmax = -1e30f;
            if (j == qt) {   // mask only on the diagonal tile
                #pragma unroll
                for (int nt = 0; nt < 8; nt++) {
                    if (kt0 + nt * 8 + 2 * t     > rowg) acc_s[nt][2 * hh]     = -1e30f;
                    if (kt0 + nt * 8 + 2 * t + 1 > rowg) acc_s[nt][2 * hh + 1] = -1e30f;
                }
            }
            #pragma unroll
            for (int nt = 0; nt < 8; nt++)
                rmax = fmaxf(rmax, fmaxf(acc_s[nt][2 * hh], acc_s[nt][2 * hh + 1]));
            rmax = fmaxf(rmax, __shfl_xor_sync(0xffffffffu, rmax, 1));
            rmax = fmaxf(rmax, __shfl_xor_sync(0xffffffffu, rmax, 2));
            float mnew  = fmaxf(mrow[hh], rmax);
            float alpha = ex2f(mrow[hh] - mnew);
            mrow[hh] = mnew;
            float rsum = 0.f;
            #pragma unroll
            for (int nt = 0; nt < 8; nt++) {
                float p0 = ex2f(acc_s[nt][2 * hh]     - mnew);
                float p1 = ex2f(acc_s[nt][2 * hh + 1] - mnew);
                acc_s[nt][2 * hh]     = p0;
                acc_s[nt][2 * hh + 1] = p1;
                rsum += p0 + p1;
                acc_o[nt][2 * hh]     *= alpha;
                acc_o[nt][2 * hh + 1] *= alpha;
            }
            rsum += __shfl_xor_sync(0xffffffffu, rsum, 1);
            rsum += __shfl_xor_sync(0xffffffffu, rsum, 2);
            lrow[hh] = lrow[hh] * alpha + rsum;
        }

        __syncthreads();   // all warps done reading Ks as K

        // ---- P (fp16) into the K buffer: [row][key], stride 72 ----
        char* Ps = smraw + KSOFF(buf);
        #pragma unroll
        for (int nt = 0; nt < 8; nt++) {
            int col = nt * 8 + 2 * t;
            *(__half2*)(Ps + ((w * 16 + g    ) * 72 + col) * 2) =
                __floats2half2_rn(acc_s[nt][0], acc_s[nt][1]);
            *(__half2*)(Ps + ((w * 16 + g + 8) * 72 + col) * 2) =
                __floats2half2_rn(acc_s[nt][2], acc_s[nt][3]);
        }
        __syncwarp();      // P rows are warp-private

        // ---- O += P @ V  (V via ldmatrix.trans from natural layout) ----
        #pragma unroll
        for (int ks = 0; ks < 4; ks++) {
            uint32_t ap[4], bv[4][4];
            ldsm_x4(ap, sb + KSOFF(buf) +
                    ((w * 16 + a_row) * 72 + ks * 16 + a_k8) * 2);
            #pragma unroll
            for (int nt2 = 0; nt2 < 4; nt2++)
                ldsm_x4_t(bv[nt2], sb + VSOFF(buf) +
                          ((ks * 16 + v_k) * 72 + nt2 * 16 + v_c) * 2);
            #pragma unroll
            for (int nt = 0; nt < 8; nt++)
                mma_f16(acc_o[nt], ap,
                        bv[nt >> 1][(nt & 1) * 2],
                        bv[nt >> 1][(nt & 1) * 2 + 1]);
        }
        buf ^= 1;
    }

    // ---- epilogue: normalize, store fp16 ----
    #pragma unroll
    for (int hh = 0; hh < 2; hh++) {
        float inv = 1.f / lrow[hh];
        int row = t0 + w * 16 + g + hh * 8;
        #pragma unroll
        for (int nt = 0; nt < 8; nt++) {
            *(__half2*)(o + base + (size_t)row * C_ + nt * 8 + 2 * t) =
                __floats2half2_rn(acc_o[nt][2 * hh] * inv,
                                  acc_o[nt][2 * hh + 1] * inv);
        }
    }
}

// ---------------- launch ----------------
extern "C" void kernel_launch(void* const* d_in, const int* in_sizes, int n_in,
                              void* d_out, int out_size) {
    const float* x    = (const float*)d_in[0];
    const float* Wq   = (const float*)d_in[1];
    const float* Wk   = (const float*)d_in[2];
    const float* Wv   = (const float*)d_in[3];
    const float* Wo   = (const float*)d_in[4];
    const float* bo   = (const float*)d_in[5];
    const float* ln1g = (const float*)d_in[6];
    const float* ln1b = (const float*)d_in[7];
    const float* ln2g = (const float*)d_in[8];
    const float* ln2b = (const float*)d_in[9];
    const float* W1   = (const float*)d_in[10];
    const float* b1   = (const float*)d_in[11];
    const float* W2   = (const float*)d_in[12];
    const float* b2   = (const float*)d_in[13];
    float* out = (float*)d_out;

    __half *h, *q, *k, *v, *att, *h2, *ff1;
    __half *wq, *wk, *wv, *wo, *w1, *w2;
    float *x2;
    cudaGetSymbolAddress((void**)&h,   g_h);
    cudaGetSymbolAddress((void**)&q,   g_q);
    cudaGetSymbolAddress((void**)&k,   g_k);
    cudaGetSymbolAddress((void**)&v,   g_v);
    cudaGetSymbolAddress((void**)&att, g_att);
    cudaGetSymbolAddress((void**)&x2,  g_x2);
    cudaGetSymbolAddress((void**)&h2,  g_h2);
    cudaGetSymbolAddress((void**)&ff1, g_ff1);
    cudaGetSymbolAddress((void**)&wq,  g_wq);
    cudaGetSymbolAddress((void**)&wk,  g_wk);
    cudaGetSymbolAddress((void**)&wv,  g_wv);
    cudaGetSymbolAddress((void**)&wo,  g_wo);
    cudaGetSymbolAddress((void**)&w1,  g_w1);
    cudaGetSymbolAddress((void**)&w2,  g_w2);

    cudaFuncSetAttribute(gemm_h<0>, cudaFuncAttributeMaxDynamicSharedMemorySize, GEMM_SMEM_BYTES);
    cudaFuncSetAttribute(gemm_h<1>, cudaFuncAttributeMaxDynamicSharedMemorySize, GEMM_SMEM_BYTES);
    cudaFuncSetAttribute(gemm_h<2>, cudaFuncAttributeMaxDynamicSharedMemorySize, GEMM_SMEM_BYTES);
    cudaFuncSetAttribute(gemm_h_qkv, cudaFuncAttributeMaxDynamicSharedMemorySize, GEMM_SMEM_BYTES);
    cudaFuncSetAttribute(attn_h_kernel, cudaFuncAttributeMaxDynamicSharedMemorySize, ATT_SMEM_BYTES);

    // 0. convert + transpose weights -> fp16 [N][K]
    cvt_t_kernel<<<12288, 256>>>(Wq, Wk, Wv, Wo, W1, W2, wq, wk, wv, wo, w1, w2);

    // 1. h = LN1(x)  (fp16 out)
    ln_kernel<<<NR, 256>>>(x, ln1g, ln1b, h);

    // 2. q,k,v = h @ {Wq,Wk,Wv}  (fp16; q pre-scaled by QSCALE)
    gemm_h_qkv<<<dim3(C_ / 128, NR / 128, 3), 128, GEMM_SMEM_BYTES>>>(
        h, wq, wk, wv, q, k, v, NR, C_, C_);

    // 3. causal attention (fp16, exp2 softmax)
    attn_h_kernel<<<dim3(T_ / 64, B_ * H_), 128, ATT_SMEM_BYTES>>>(q, k, v, att);

    // 4. x2 = x + att @ Wo + bo  (fp32 out)
    gemm_h<2><<<dim3(C_ / 128, NR / 128), 128, GEMM_SMEM_BYTES>>>(att, wo, bo, x, x2, NR, C_, C_);

    // 5. h2 = LN2(x2)  (fp16 out)
    ln_kernel<<<NR, 256>>>(x2, ln2g, ln2b, h2);

    // 6. ff1 = relu(h2 @ W1 + b1)  (fp16 out)
    gemm_h<1><<<dim3(FF / 128, NR / 128), 128, GEMM_SMEM_BYTES>>>(h2, w1, b1, nullptr, ff1, NR, FF, C_);

    // 7. out = x2 + ff1 @ W2 + b2  (fp32 out)
    gemm_h<2><<<dim3(C_ / 128, NR / 128), 128, GEMM_SMEM_BYTES>>>(ff1, w2, b2, x2, out, NR, C_, FF);
}